// round 1
// baseline (speedup 1.0000x reference)
#include <cuda_runtime.h>
#include <math.h>

#define BATCH   8
#define SEQ     2048
#define EMB     768
#define NHEADS  12
#define HDIM    64
#define BS_TOT  (BATCH * SEQ)      // 16384

// Scratch (alloc-free rules): q, k, v, z each [BS_TOT, EMB] fp32
__device__ float g_q[BS_TOT * EMB];
__device__ float g_k[BS_TOT * EMB];
__device__ float g_v[BS_TOT * EMB];
__device__ float g_z[BS_TOT * EMB];

// ---------------------------------------------------------------------------
// GEMM: C[M,N] = A[M,K] @ B + bias(per column)
// QKV=true : B is W_{Q,K,V} with layout [N/64][K][64] (i.e. [n][e][h], H=64)
// QKV=false: B is row-major [K][N] (W_O reshaped [n*h][e])
// Tile 64x64x16, 128 threads, 4x8 micro-tile per thread.
// ---------------------------------------------------------------------------
template <bool QKV>
__global__ __launch_bounds__(128) void gemm_kernel(
    const float* __restrict__ A, const float* __restrict__ Bm,
    const float* __restrict__ bias, float* __restrict__ C,
    int M, int N, int K)
{
    __shared__ float As[16][68];   // stored transposed: As[kk][m]
    __shared__ float Bs[16][64];   // Bs[kk][n]

    const int tid = threadIdx.x;
    const int m0  = blockIdx.y * 64;
    const int n0  = blockIdx.x * 64;
    const int mi  = (tid >> 3) * 4;   // 16 row groups
    const int nj  = (tid & 7) * 8;    // 8 col groups
    const int lar = tid >> 1;         // A load: row 0..63
    const int lak = (tid & 1) * 8;    // A load: 8 k's
    const int lbk = tid >> 3;         // B load: k 0..15
    const int lbn = (tid & 7) * 8;    // B load: 8 n's

    float acc[4][8];
#pragma unroll
    for (int i = 0; i < 4; i++)
#pragma unroll
        for (int j = 0; j < 8; j++) acc[i][j] = 0.f;

    for (int k0 = 0; k0 < K; k0 += 16) {
        const float* ap = A + (size_t)(m0 + lar) * K + k0 + lak;
        float4 a0 = *(const float4*)ap;
        float4 a1 = *(const float4*)(ap + 4);
        const float* bp;
        if (QKV)
            bp = Bm + ((size_t)(n0 >> 6) * K + (k0 + lbk)) * 64 + lbn;
        else
            bp = Bm + (size_t)(k0 + lbk) * N + n0 + lbn;
        float4 b0 = *(const float4*)bp;
        float4 b1 = *(const float4*)(bp + 4);

        __syncthreads();  // previous tile's compute done
        As[lak + 0][lar] = a0.x; As[lak + 1][lar] = a0.y;
        As[lak + 2][lar] = a0.z; As[lak + 3][lar] = a0.w;
        As[lak + 4][lar] = a1.x; As[lak + 5][lar] = a1.y;
        As[lak + 6][lar] = a1.z; As[lak + 7][lar] = a1.w;
        *(float4*)&Bs[lbk][lbn]     = b0;
        *(float4*)&Bs[lbk][lbn + 4] = b1;
        __syncthreads();

#pragma unroll
        for (int kk = 0; kk < 16; kk++) {
            float4 av  = *(const float4*)&As[kk][mi];
            float4 bv0 = *(const float4*)&Bs[kk][nj];
            float4 bv1 = *(const float4*)&Bs[kk][nj + 4];
            float a[4] = {av.x, av.y, av.z, av.w};
            float b[8] = {bv0.x, bv0.y, bv0.z, bv0.w, bv1.x, bv1.y, bv1.z, bv1.w};
#pragma unroll
            for (int i = 0; i < 4; i++)
#pragma unroll
                for (int j = 0; j < 8; j++)
                    acc[i][j] += a[i] * b[j];
        }
    }

#pragma unroll
    for (int i = 0; i < 4; i++) {
        size_t row = (size_t)(m0 + mi + i) * N + n0 + nj;
#pragma unroll
        for (int j = 0; j < 8; j++)
            C[row + j] = acc[i][j] + bias[n0 + nj + j];
    }
}

// ---------------------------------------------------------------------------
// Flash attention (causal), fp32. One block = (b, n, 64-query tile).
// Key tiles of 32. 128 threads. Static smem 44.6 KB.
// q/k/v layout: [b*S + s][n*64 + d]. Scale 1/8 folded into Q at load.
// ---------------------------------------------------------------------------
__global__ __launch_bounds__(128) void attn_kernel(
    const float* __restrict__ q, const float* __restrict__ k,
    const float* __restrict__ v, float* __restrict__ z)
{
    __shared__ float Qs[64][68];   // Qs[d][i]
    __shared__ float Ss[64][36];   // scores/probs [i][j]
    __shared__ float Ks[64][36];   // Ks[d][j]
    __shared__ float Vs[32][64];   // Vs[j][d]
    __shared__ float m_sh[64], l_sh[64], a_sh[64];

    const int tid = threadIdx.x;
    const int qt = blockIdx.x, n = blockIdx.y, b = blockIdx.z;
    const int q_base = qt * 64;
    const size_t base_bn = (size_t)b * SEQ * EMB + (size_t)n * HDIM;

    // Load & scale Q tile (transposed into Qs[d][i])
    for (int idx = tid; idx < 64 * 64; idx += 128) {
        int i = idx >> 6, d = idx & 63;
        Qs[d][i] = q[base_bn + (size_t)(q_base + i) * EMB + d] * 0.125f;
    }
    if (tid < 64) { m_sh[tid] = -INFINITY; l_sh[tid] = 0.f; }

    const int mi  = (tid >> 3) * 4;  // 4 query rows
    const int njs = (tid & 7) * 4;   // 4 score cols (key tile = 32)
    const int dj  = (tid & 7) * 8;   // 8 output dims

    float o[4][8];
#pragma unroll
    for (int i = 0; i < 4; i++)
#pragma unroll
        for (int j = 0; j < 8; j++) o[i][j] = 0.f;

    const int nkt = 2 * qt + 2;   // 32-wide key tiles up to & incl. diagonal
    for (int kt = 0; kt < nkt; kt++) {
        __syncthreads();  // previous tile fully consumed
        for (int idx = tid; idx < 32 * 64; idx += 128) {
            int j = idx >> 6, d = idx & 63;
            size_t g = base_bn + (size_t)(kt * 32 + j) * EMB + d;
            Ks[d][j] = k[g];
            Vs[j][d] = v[g];
        }
        __syncthreads();

        // ---- scores: S[i][j] = Q_row_i . K_col_j (Q pre-scaled) ----
        float s[4][4];
#pragma unroll
        for (int i = 0; i < 4; i++)
#pragma unroll
            for (int j = 0; j < 4; j++) s[i][j] = 0.f;
#pragma unroll 8
        for (int d = 0; d < 64; d++) {
            float4 qa = *(const float4*)&Qs[d][mi];
            float4 kb = *(const float4*)&Ks[d][njs];
            float a[4] = {qa.x, qa.y, qa.z, qa.w};
            float c[4] = {kb.x, kb.y, kb.z, kb.w};
#pragma unroll
            for (int i = 0; i < 4; i++)
#pragma unroll
                for (int j = 0; j < 4; j++)
                    s[i][j] += a[i] * c[j];
        }
        if (kt >= 2 * qt) {  // diagonal region: apply causal mask
#pragma unroll
            for (int i = 0; i < 4; i++)
#pragma unroll
                for (int j = 0; j < 4; j++) {
                    int ig = q_base + mi + i;
                    int jg = kt * 32 + njs + j;
                    if (jg > ig) s[i][j] = -1e30f;
                }
        }
#pragma unroll
        for (int i = 0; i < 4; i++)
            *(float4*)&Ss[mi + i][njs] =
                make_float4(s[i][0], s[i][1], s[i][2], s[i][3]);
        __syncthreads();

        // ---- online softmax (one thread per query row) ----
        if (tid < 64) {
            float mold = m_sh[tid];
            float mt = mold;
#pragma unroll 8
            for (int j = 0; j < 32; j++) mt = fmaxf(mt, Ss[tid][j]);
            float alpha = __expf(mold - mt);   // exp(-inf)=0 on first tile
            float l = l_sh[tid] * alpha;
#pragma unroll 8
            for (int j = 0; j < 32; j++) {
                float p = __expf(Ss[tid][j] - mt);
                l += p;
                Ss[tid][j] = p;
            }
            m_sh[tid] = mt; l_sh[tid] = l; a_sh[tid] = alpha;
        }
        __syncthreads();

        // ---- rescale accumulators, then O += P @ V ----
        float al[4];
#pragma unroll
        for (int i = 0; i < 4; i++) al[i] = a_sh[mi + i];
#pragma unroll
        for (int i = 0; i < 4; i++)
#pragma unroll
            for (int j = 0; j < 8; j++) o[i][j] *= al[i];
#pragma unroll 4
        for (int j = 0; j < 32; j++) {
            float p[4];
#pragma unroll
            for (int i = 0; i < 4; i++) p[i] = Ss[mi + i][j];
            float4 v0 = *(const float4*)&Vs[j][dj];
            float4 v1 = *(const float4*)&Vs[j][dj + 4];
            float vv[8] = {v0.x, v0.y, v0.z, v0.w, v1.x, v1.y, v1.z, v1.w};
#pragma unroll
            for (int i = 0; i < 4; i++)
#pragma unroll
                for (int jj = 0; jj < 8; jj++)
                    o[i][jj] += p[i] * vv[jj];
        }
    }
    __syncthreads();

    float inv[4];
#pragma unroll
    for (int i = 0; i < 4; i++) inv[i] = 1.f / l_sh[mi + i];
#pragma unroll
    for (int i = 0; i < 4; i++) {
        size_t g = base_bn + (size_t)(q_base + mi + i) * EMB + dj;
#pragma unroll
        for (int j = 0; j < 8; j++)
            z[g + j] = o[i][j] * inv[i];
    }
}

// ---------------------------------------------------------------------------
extern "C" void kernel_launch(void* const* d_in, const int* in_sizes, int n_in,
                              void* d_out, int out_size)
{
    const float* x  = (const float*)d_in[0];
    const float* WQ = (const float*)d_in[1];
    const float* WK = (const float*)d_in[2];
    const float* WV = (const float*)d_in[3];
    const float* WO = (const float*)d_in[4];
    const float* bQ = (const float*)d_in[5];
    const float* bK = (const float*)d_in[6];
    const float* bV = (const float*)d_in[7];
    const float* bO = (const float*)d_in[8];
    float* out = (float*)d_out;

    float *qp, *kp, *vp, *zp;
    cudaGetSymbolAddress((void**)&qp, g_q);
    cudaGetSymbolAddress((void**)&kp, g_k);
    cudaGetSymbolAddress((void**)&vp, g_v);
    cudaGetSymbolAddress((void**)&zp, g_z);

    dim3 ggrid(EMB / 64, BS_TOT / 64);
    gemm_kernel<true><<<ggrid, 128>>>(x, WQ, bQ, qp, BS_TOT, EMB, EMB);
    gemm_kernel<true><<<ggrid, 128>>>(x, WK, bK, kp, BS_TOT, EMB, EMB);
    gemm_kernel<true><<<ggrid, 128>>>(x, WV, bV, vp, BS_TOT, EMB, EMB);

    attn_kernel<<<dim3(SEQ / 64, NHEADS, BATCH), 128>>>(qp, kp, vp, zp);

    gemm_kernel<false><<<ggrid, 128>>>(zp, WO, bO, out, BS_TOT, EMB, EMB);
}

// round 3
// speedup vs baseline: 3.3245x; 3.3245x over previous
#include <cuda_runtime.h>
#include <math.h>
#include <cstdint>

#define BATCH   8
#define SEQ     2048
#define EMB     768
#define NHEADS  12
#define HDIM    64
#define BS_TOT  (BATCH * SEQ)      // 16384

// Scratch (alloc-free rules): q, k, v, z each [BS_TOT, EMB] fp32
__device__ float g_q[BS_TOT * EMB];
__device__ float g_k[BS_TOT * EMB];
__device__ float g_v[BS_TOT * EMB];
__device__ float g_z[BS_TOT * EMB];

// ===========================================================================
// Helpers: tf32 rounding + m16n8k8 tf32 MMA (sm_80+ baseline PTX, works on
// compute_103 non-'a' target; tcgen05 is NOT available in this build).
// ===========================================================================
__device__ __forceinline__ float tf32r(float x) {
    uint32_t u;
    asm("cvt.rna.tf32.f32 %0, %1;" : "=r"(u) : "f"(x));
    return __uint_as_float(u);
}
__device__ __forceinline__ uint32_t fu(float x) { return __float_as_uint(x); }

// D += A(16x8,row) * B(8x8,col).  acc in fp32.
__device__ __forceinline__ void mma_tf32(float* d, const uint32_t* a,
                                         const uint32_t* b) {
    asm volatile(
        "mma.sync.aligned.m16n8k8.row.col.f32.tf32.tf32.f32 "
        "{%0,%1,%2,%3}, {%4,%5,%6,%7}, {%8,%9}, {%0,%1,%2,%3};"
        : "+f"(d[0]), "+f"(d[1]), "+f"(d[2]), "+f"(d[3])
        : "r"(a[0]), "r"(a[1]), "r"(a[2]), "r"(a[3]),
          "r"(b[0]), "r"(b[1]));
}

// ===========================================================================
// tf32 tensor-core GEMM: C[M,N] = A[M,K] @ B + bias
// QKV=true : B layout [N/64][K][64]  (W_{Q,K,V} [n][e][h], H=64)
// QKV=false: B layout [K][N] row-major (W_O reshaped)
// CTA tile 128x128, BK=32, 256 threads (8 warps x 64x32), reg-prefetch.
// smem pitch 36 floats -> fragment loads conflict-free (banks = 4*g + t).
// ===========================================================================
#define GP   36
#define NST  (EMB / 32)   // 24
#define GEMM_SMEM (2 * 128 * GP * 4)   // 36864 B

template <bool QKV>
__global__ __launch_bounds__(256) void gemm_tc(
    const float* __restrict__ A, const float* __restrict__ Bm,
    const float* __restrict__ bias, float* __restrict__ C,
    int M, int N, int K)
{
    extern __shared__ float sm[];
    float* As = sm;             // [128][GP]
    float* Bs = sm + 128 * GP;  // [128][GP]  (n-major, k cols)

    const int tid = threadIdx.x;
    const int wid = tid >> 5, lane = tid & 31;
    const int wr = wid >> 2, wc = wid & 3;
    const int gr = lane >> 2, tg = lane & 3;
    const int m0 = blockIdx.y * 128, n0 = blockIdx.x * 128;

    float acc[4][4][4];
#pragma unroll
    for (int mt = 0; mt < 4; mt++)
#pragma unroll
        for (int nt = 0; nt < 4; nt++)
#pragma unroll
            for (int i = 0; i < 4; i++) acc[mt][nt][i] = 0.f;

    float4 pa[4], pb[4];

    auto loadG = [&](int s) {
        const int k0 = s * 32;
#pragma unroll
        for (int i = 0; i < 4; i++) {
            int idx = tid + i * 256;
            int row = idx >> 3, kq = idx & 7;
            pa[i] = *(const float4*)(A + (size_t)(m0 + row) * K + k0 + kq * 4);
        }
#pragma unroll
        for (int i = 0; i < 4; i++) {
            int idx = tid + i * 256;
            int row = idx & 127, kq = idx >> 7;
            int nn = n0 + row, kk = k0 + kq * 4;
            float4 v;
            if (QKV) {
                const float* bp = Bm + ((size_t)(nn >> 6) * K + kk) * 64 + (nn & 63);
                v.x = bp[0]; v.y = bp[64]; v.z = bp[128]; v.w = bp[192];
            } else {
                const float* bp = Bm + (size_t)kk * N + nn;
                v.x = bp[0]; v.y = bp[N]; v.z = bp[2 * N]; v.w = bp[3 * N];
            }
            pb[i] = v;
        }
    };
    auto r2s = [&]() {
#pragma unroll
        for (int i = 0; i < 4; i++) {
            int idx = tid + i * 256;
            int row = idx >> 3, kq = idx & 7;
            float4 v = pa[i];
            v.x = tf32r(v.x); v.y = tf32r(v.y);
            v.z = tf32r(v.z); v.w = tf32r(v.w);
            *(float4*)&As[row * GP + kq * 4] = v;
        }
#pragma unroll
        for (int i = 0; i < 4; i++) {
            int idx = tid + i * 256;
            int row = idx & 127, kq = idx >> 7;
            float4 v = pb[i];
            v.x = tf32r(v.x); v.y = tf32r(v.y);
            v.z = tf32r(v.z); v.w = tf32r(v.w);
            *(float4*)&Bs[row * GP + kq * 4] = v;
        }
    };

    loadG(0);
    r2s();
    __syncthreads();

    for (int s = 0; s < NST; s++) {
        if (s + 1 < NST) loadG(s + 1);
#pragma unroll
        for (int ks = 0; ks < 4; ks++) {
            const int k0 = ks * 8;
            uint32_t af[4][4], bf[4][2];
#pragma unroll
            for (int mt = 0; mt < 4; mt++) {
                int r = wr * 64 + mt * 16 + gr;
                af[mt][0] = fu(As[r * GP + k0 + tg]);
                af[mt][1] = fu(As[(r + 8) * GP + k0 + tg]);
                af[mt][2] = fu(As[r * GP + k0 + tg + 4]);
                af[mt][3] = fu(As[(r + 8) * GP + k0 + tg + 4]);
            }
#pragma unroll
            for (int nt = 0; nt < 4; nt++) {
                int c = wc * 32 + nt * 8 + gr;
                bf[nt][0] = fu(Bs[c * GP + k0 + tg]);
                bf[nt][1] = fu(Bs[c * GP + k0 + tg + 4]);
            }
#pragma unroll
            for (int mt = 0; mt < 4; mt++)
#pragma unroll
                for (int nt = 0; nt < 4; nt++)
                    mma_tf32(acc[mt][nt], af[mt], bf[nt]);
        }
        __syncthreads();
        if (s + 1 < NST) { r2s(); __syncthreads(); }
    }

    // ---- epilogue: c0:(r, 2t), c1:(r, 2t+1), c2:(r+8, 2t), c3:(r+8, 2t+1) --
#pragma unroll
    for (int mt = 0; mt < 4; mt++)
#pragma unroll
        for (int nt = 0; nt < 4; nt++) {
            int r = m0 + wr * 64 + mt * 16 + gr;
            int c = n0 + wc * 32 + nt * 8 + tg * 2;
            float b0 = bias[c], b1 = bias[c + 1];
            float2 v0 = make_float2(acc[mt][nt][0] + b0, acc[mt][nt][1] + b1);
            float2 v1 = make_float2(acc[mt][nt][2] + b0, acc[mt][nt][3] + b1);
            *(float2*)(C + (size_t)r * N + c) = v0;
            *(float2*)(C + (size_t)(r + 8) * N + c) = v1;
        }
}

// ===========================================================================
// Flash attention (causal), tf32 MMA for QK^T and PV; scalar softmax in smem.
// One block = (b, head, 64-query tile); key tiles of 32; 128 threads (4 warps).
// Warp w owns query rows [16w, 16w+16).
// ===========================================================================
__global__ __launch_bounds__(128) void attn_tc(
    const float* __restrict__ q, const float* __restrict__ k,
    const float* __restrict__ v, float* __restrict__ z)
{
    __shared__ float Qs[64 * 68];   // [q][d]   pitch 68
    __shared__ float Ks[32 * 68];   // [key][d] pitch 68
    __shared__ float Vs[32 * 68];   // [key][d] pitch 68
    __shared__ float Ss[64 * 36];   // [q][key] pitch 36
    __shared__ float m_sh[64], l_sh[64], a_sh[64];

    const int tid = threadIdx.x;
    const int w = tid >> 5, lane = tid & 31;
    const int gr = lane >> 2, tg = lane & 3;
    const int qt = blockIdx.x, hn = blockIdx.y, b = blockIdx.z;
    const int q_base = qt * 64;
    const size_t base_bn = (size_t)b * SEQ * EMB + (size_t)hn * HDIM;

    // ---- load Q (scaled by 1/8, tf32-rounded) ----
#pragma unroll
    for (int i = 0; i < 8; i++) {
        int idx = tid + i * 128;
        int row = idx >> 4, dq = idx & 15;
        float4 x = *(const float4*)(q + base_bn + (size_t)(q_base + row) * EMB + dq * 4);
        x.x = tf32r(x.x * 0.125f); x.y = tf32r(x.y * 0.125f);
        x.z = tf32r(x.z * 0.125f); x.w = tf32r(x.w * 0.125f);
        *(float4*)&Qs[row * 68 + dq * 4] = x;
    }
    if (tid < 64) { m_sh[tid] = -INFINITY; l_sh[tid] = 0.f; }

    float o[8][4];
#pragma unroll
    for (int nt = 0; nt < 8; nt++)
#pragma unroll
        for (int i = 0; i < 4; i++) o[nt][i] = 0.f;

    const int nkt = 2 * qt + 2;
    __syncthreads();

    for (int kt = 0; kt < nkt; kt++) {
        // ---- load K,V tiles [32 keys x 64 d] ----
#pragma unroll
        for (int i = 0; i < 4; i++) {
            int idx = tid + i * 128;
            int row = idx >> 4, dq = idx & 15;
            size_t g = base_bn + (size_t)(kt * 32 + row) * EMB + dq * 4;
            float4 kk = *(const float4*)(k + g);
            kk.x = tf32r(kk.x); kk.y = tf32r(kk.y);
            kk.z = tf32r(kk.z); kk.w = tf32r(kk.w);
            *(float4*)&Ks[row * 68 + dq * 4] = kk;
            float4 vv = *(const float4*)(v + g);
            vv.x = tf32r(vv.x); vv.y = tf32r(vv.y);
            vv.z = tf32r(vv.z); vv.w = tf32r(vv.w);
            *(float4*)&Vs[row * 68 + dq * 4] = vv;
        }
        __syncthreads();

        // ---- scores: S[16 rows x 32 keys] per warp, k=64 (8 ksteps) ----
        float sc[4][4];
#pragma unroll
        for (int nt = 0; nt < 4; nt++)
#pragma unroll
            for (int i = 0; i < 4; i++) sc[nt][i] = 0.f;
#pragma unroll
        for (int ks = 0; ks < 8; ks++) {
            const int k0 = ks * 8;
            const int r = w * 16 + gr;
            uint32_t af[4], bf[4][2];
            af[0] = fu(Qs[r * 68 + k0 + tg]);
            af[1] = fu(Qs[(r + 8) * 68 + k0 + tg]);
            af[2] = fu(Qs[r * 68 + k0 + tg + 4]);
            af[3] = fu(Qs[(r + 8) * 68 + k0 + tg + 4]);
#pragma unroll
            for (int nt = 0; nt < 4; nt++) {
                int c = nt * 8 + gr;
                bf[nt][0] = fu(Ks[c * 68 + k0 + tg]);
                bf[nt][1] = fu(Ks[c * 68 + k0 + tg + 4]);
            }
#pragma unroll
            for (int nt = 0; nt < 4; nt++)
                mma_tf32(sc[nt], af, bf[nt]);
        }
        // write scores to smem
#pragma unroll
        for (int nt = 0; nt < 4; nt++) {
            int r = w * 16 + gr, c = nt * 8 + tg * 2;
            *(float2*)&Ss[r * 36 + c] = make_float2(sc[nt][0], sc[nt][1]);
            *(float2*)&Ss[(r + 8) * 36 + c] = make_float2(sc[nt][2], sc[nt][3]);
        }
        __syncthreads();

        // ---- online softmax (one thread per query row; mask inline) ----
        if (tid < 64) {
            const int ig = q_base + tid;
            const int jbase = kt * 32;
            const bool diag = (kt >= 2 * qt);
            float mold = m_sh[tid], mt_ = mold;
#pragma unroll 8
            for (int j = 0; j < 32; j++) {
                float sj = Ss[tid * 36 + j];
                if (diag && jbase + j > ig) sj = -1e30f;
                mt_ = fmaxf(mt_, sj);
            }
            float alpha = __expf(mold - mt_);   // exp(-inf)=0 on first tile
            float l = l_sh[tid] * alpha;
#pragma unroll 8
            for (int j = 0; j < 32; j++) {
                float sj = Ss[tid * 36 + j];
                if (diag && jbase + j > ig) sj = -1e30f;
                float p = __expf(sj - mt_);
                l += p;
                Ss[tid * 36 + j] = tf32r(p);
            }
            m_sh[tid] = mt_; l_sh[tid] = l; a_sh[tid] = alpha;
        }
        __syncthreads();

        // ---- rescale O, then O += P @ V (k=32 keys, 4 ksteps, 8 d-tiles) --
        float al0 = a_sh[w * 16 + gr], al1 = a_sh[w * 16 + gr + 8];
#pragma unroll
        for (int nt = 0; nt < 8; nt++) {
            o[nt][0] *= al0; o[nt][1] *= al0;
            o[nt][2] *= al1; o[nt][3] *= al1;
        }
#pragma unroll
        for (int ks = 0; ks < 4; ks++) {
            const int k0 = ks * 8;
            const int r = w * 16 + gr;
            uint32_t af[4];
            af[0] = fu(Ss[r * 36 + k0 + tg]);
            af[1] = fu(Ss[(r + 8) * 36 + k0 + tg]);
            af[2] = fu(Ss[r * 36 + k0 + tg + 4]);
            af[3] = fu(Ss[(r + 8) * 36 + k0 + tg + 4]);
#pragma unroll
            for (int nt = 0; nt < 8; nt++) {
                uint32_t bf[2];
                bf[0] = fu(Vs[(k0 + tg) * 68 + nt * 8 + gr]);
                bf[1] = fu(Vs[(k0 + tg + 4) * 68 + nt * 8 + gr]);
                mma_tf32(o[nt], af, bf);
            }
        }
        __syncthreads();   // before next K/V overwrite
    }

    // ---- normalize & store ----
    const float inv0 = 1.f / l_sh[w * 16 + gr];
    const float inv1 = 1.f / l_sh[w * 16 + gr + 8];
    const int r0 = q_base + w * 16 + gr;
#pragma unroll
    for (int nt = 0; nt < 8; nt++) {
        int d = nt * 8 + tg * 2;
        size_t g0 = base_bn + (size_t)r0 * EMB + d;
        size_t g1 = base_bn + (size_t)(r0 + 8) * EMB + d;
        *(float2*)(z + g0) = make_float2(o[nt][0] * inv0, o[nt][1] * inv0);
        *(float2*)(z + g1) = make_float2(o[nt][2] * inv1, o[nt][3] * inv1);
    }
}

// ---------------------------------------------------------------------------
extern "C" void kernel_launch(void* const* d_in, const int* in_sizes, int n_in,
                              void* d_out, int out_size)
{
    const float* x  = (const float*)d_in[0];
    const float* WQ = (const float*)d_in[1];
    const float* WK = (const float*)d_in[2];
    const float* WV = (const float*)d_in[3];
    const float* WO = (const float*)d_in[4];
    const float* bQ = (const float*)d_in[5];
    const float* bK = (const float*)d_in[6];
    const float* bV = (const float*)d_in[7];
    const float* bO = (const float*)d_in[8];
    float* out = (float*)d_out;

    float *qp, *kp, *vp, *zp;
    cudaGetSymbolAddress((void**)&qp, g_q);
    cudaGetSymbolAddress((void**)&kp, g_k);
    cudaGetSymbolAddress((void**)&vp, g_v);
    cudaGetSymbolAddress((void**)&zp, g_z);

    dim3 ggrid(EMB / 128, BS_TOT / 128);   // 6 x 128
    gemm_tc<true><<<ggrid, 256, GEMM_SMEM>>>(x, WQ, bQ, qp, BS_TOT, EMB, EMB);
    gemm_tc<true><<<ggrid, 256, GEMM_SMEM>>>(x, WK, bK, kp, BS_TOT, EMB, EMB);
    gemm_tc<true><<<ggrid, 256, GEMM_SMEM>>>(x, WV, bV, vp, BS_TOT, EMB, EMB);

    attn_tc<<<dim3(SEQ / 64, NHEADS, BATCH), 128>>>(qp, kp, vp, zp);

    gemm_tc<false><<<ggrid, 256, GEMM_SMEM>>>(zp, WO, bO, out, BS_TOT, EMB, EMB);
}

// round 4
// speedup vs baseline: 4.3942x; 1.3217x over previous
#include <cuda_runtime.h>
#include <math.h>
#include <cstdint>

#define BATCH   8
#define SEQ     2048
#define EMB     768
#define NHEADS  12
#define HDIM    64
#define BS_TOT  (BATCH * SEQ)      // 16384

// Scratch (alloc-free rules): q, k, v, z each [BS_TOT, EMB] fp32
__device__ float g_q[BS_TOT * EMB];
__device__ float g_k[BS_TOT * EMB];
__device__ float g_v[BS_TOT * EMB];
__device__ float g_z[BS_TOT * EMB];

// ===========================================================================
// Helpers: tf32 rounding + m16n8k8 tf32 MMA (sm_80+ baseline PTX; tcgen05 is
// unavailable on the compute_103 non-'a' target this harness uses).
// ===========================================================================
__device__ __forceinline__ float tf32r(float x) {
    uint32_t u;
    asm("cvt.rna.tf32.f32 %0, %1;" : "=r"(u) : "f"(x));
    return __uint_as_float(u);
}
__device__ __forceinline__ uint32_t fu(float x) { return __float_as_uint(x); }
__device__ __forceinline__ uint32_t tf32u(float x) {
    uint32_t u;
    asm("cvt.rna.tf32.f32 %0, %1;" : "=r"(u) : "f"(x));
    return u;
}

// D += A(16x8,row) * B(8x8,col).  acc in fp32.
__device__ __forceinline__ void mma_tf32(float* d, const uint32_t* a,
                                         const uint32_t* b) {
    asm volatile(
        "mma.sync.aligned.m16n8k8.row.col.f32.tf32.tf32.f32 "
        "{%0,%1,%2,%3}, {%4,%5,%6,%7}, {%8,%9}, {%0,%1,%2,%3};"
        : "+f"(d[0]), "+f"(d[1]), "+f"(d[2]), "+f"(d[3])
        : "r"(a[0]), "r"(a[1]), "r"(a[2]), "r"(a[3]),
          "r"(b[0]), "r"(b[1]));
}

// ===========================================================================
// tf32 tensor-core GEMM: C[M,N] = A[M,K] @ B + bias  (unchanged from R3)
// ===========================================================================
#define GP   36
#define NST  (EMB / 32)   // 24
#define GEMM_SMEM (2 * 128 * GP * 4)   // 36864 B

template <bool QKV>
__global__ __launch_bounds__(256) void gemm_tc(
    const float* __restrict__ A, const float* __restrict__ Bm,
    const float* __restrict__ bias, float* __restrict__ C,
    int M, int N, int K)
{
    extern __shared__ float sm[];
    float* As = sm;             // [128][GP]
    float* Bs = sm + 128 * GP;  // [128][GP]

    const int tid = threadIdx.x;
    const int wid = tid >> 5, lane = tid & 31;
    const int wr = wid >> 2, wc = wid & 3;
    const int gr = lane >> 2, tg = lane & 3;
    const int m0 = blockIdx.y * 128, n0 = blockIdx.x * 128;

    float acc[4][4][4];
#pragma unroll
    for (int mt = 0; mt < 4; mt++)
#pragma unroll
        for (int nt = 0; nt < 4; nt++)
#pragma unroll
            for (int i = 0; i < 4; i++) acc[mt][nt][i] = 0.f;

    float4 pa[4], pb[4];

    auto loadG = [&](int s) {
        const int k0 = s * 32;
#pragma unroll
        for (int i = 0; i < 4; i++) {
            int idx = tid + i * 256;
            int row = idx >> 3, kq = idx & 7;
            pa[i] = *(const float4*)(A + (size_t)(m0 + row) * K + k0 + kq * 4);
        }
#pragma unroll
        for (int i = 0; i < 4; i++) {
            int idx = tid + i * 256;
            int row = idx & 127, kq = idx >> 7;
            int nn = n0 + row, kk = k0 + kq * 4;
            float4 v;
            if (QKV) {
                const float* bp = Bm + ((size_t)(nn >> 6) * K + kk) * 64 + (nn & 63);
                v.x = bp[0]; v.y = bp[64]; v.z = bp[128]; v.w = bp[192];
            } else {
                const float* bp = Bm + (size_t)kk * N + nn;
                v.x = bp[0]; v.y = bp[N]; v.z = bp[2 * N]; v.w = bp[3 * N];
            }
            pb[i] = v;
        }
    };
    auto r2s = [&]() {
#pragma unroll
        for (int i = 0; i < 4; i++) {
            int idx = tid + i * 256;
            int row = idx >> 3, kq = idx & 7;
            float4 v = pa[i];
            v.x = tf32r(v.x); v.y = tf32r(v.y);
            v.z = tf32r(v.z); v.w = tf32r(v.w);
            *(float4*)&As[row * GP + kq * 4] = v;
        }
#pragma unroll
        for (int i = 0; i < 4; i++) {
            int idx = tid + i * 256;
            int row = idx & 127, kq = idx >> 7;
            float4 v = pb[i];
            v.x = tf32r(v.x); v.y = tf32r(v.y);
            v.z = tf32r(v.z); v.w = tf32r(v.w);
            *(float4*)&Bs[row * GP + kq * 4] = v;
        }
    };

    loadG(0);
    r2s();
    __syncthreads();

    for (int s = 0; s < NST; s++) {
        if (s + 1 < NST) loadG(s + 1);
#pragma unroll
        for (int ks = 0; ks < 4; ks++) {
            const int k0 = ks * 8;
            uint32_t af[4][4], bf[4][2];
#pragma unroll
            for (int mt = 0; mt < 4; mt++) {
                int r = wr * 64 + mt * 16 + gr;
                af[mt][0] = fu(As[r * GP + k0 + tg]);
                af[mt][1] = fu(As[(r + 8) * GP + k0 + tg]);
                af[mt][2] = fu(As[r * GP + k0 + tg + 4]);
                af[mt][3] = fu(As[(r + 8) * GP + k0 + tg + 4]);
            }
#pragma unroll
            for (int nt = 0; nt < 4; nt++) {
                int c = wc * 32 + nt * 8 + gr;
                bf[nt][0] = fu(Bs[c * GP + k0 + tg]);
                bf[nt][1] = fu(Bs[c * GP + k0 + tg + 4]);
            }
#pragma unroll
            for (int mt = 0; mt < 4; mt++)
#pragma unroll
                for (int nt = 0; nt < 4; nt++)
                    mma_tf32(acc[mt][nt], af[mt], bf[nt]);
        }
        __syncthreads();
        if (s + 1 < NST) { r2s(); __syncthreads(); }
    }

#pragma unroll
    for (int mt = 0; mt < 4; mt++)
#pragma unroll
        for (int nt = 0; nt < 4; nt++) {
            int r = m0 + wr * 64 + mt * 16 + gr;
            int c = n0 + wc * 32 + nt * 8 + tg * 2;
            float b0 = bias[c], b1 = bias[c + 1];
            float2 v0 = make_float2(acc[mt][nt][0] + b0, acc[mt][nt][1] + b1);
            float2 v1 = make_float2(acc[mt][nt][2] + b0, acc[mt][nt][3] + b1);
            *(float2*)(C + (size_t)r * N + c) = v0;
            *(float2*)(C + (size_t)(r + 8) * N + c) = v1;
        }
}

// ===========================================================================
// Flash attention (causal), tf32 MMA, REGISTER-RESIDENT online softmax.
// One block = (b, head, 64-query tile); key tiles of 32; 128 threads, 4 warps.
// Warp w owns query rows [16w, 16w+16); all softmax state in registers
// (row spread across 4 tg-lanes; bfly shuffles for row max/sum; idx shuffles
// to re-lay-out P from C-fragment form to A-operand form).
// Ks pitch 68 (conflict-free K frags), Vs pitch 72 (conflict-free V frags).
// ===========================================================================
#define KP 68
#define VP 72

__global__ __launch_bounds__(128) void attn_tc(
    const float* __restrict__ q, const float* __restrict__ k,
    const float* __restrict__ v, float* __restrict__ z)
{
    __shared__ float sbuf[32 * KP + 32 * VP];   // 17.5 KB; Q phase aliases it
    float* Ks = sbuf;
    float* Vs = sbuf + 32 * KP;

    const int tid = threadIdx.x;
    const int w = tid >> 5, lane = tid & 31;
    const int gr = lane >> 2, tg = lane & 3;
    const int qt = blockIdx.x, hn = blockIdx.y, b = blockIdx.z;
    const int q_base = qt * 64;
    const size_t base_bn = (size_t)b * SEQ * EMB + (size_t)hn * HDIM;

    // ---- Q phase: gmem -> smem[64][68] -> register fragments (held all kernel)
#pragma unroll
    for (int i = 0; i < 8; i++) {
        int idx = tid + i * 128;
        int row = idx >> 4, dq = idx & 15;
        float4 x = *(const float4*)(q + base_bn + (size_t)(q_base + row) * EMB + dq * 4);
        x.x = tf32r(x.x * 0.125f); x.y = tf32r(x.y * 0.125f);
        x.z = tf32r(x.z * 0.125f); x.w = tf32r(x.w * 0.125f);
        *(float4*)&sbuf[row * KP + dq * 4] = x;
    }
    __syncthreads();
    uint32_t qf[8][4];
    {
        const int r = w * 16 + gr;
#pragma unroll
        for (int ks = 0; ks < 8; ks++) {
            int k0 = ks * 8;
            qf[ks][0] = fu(sbuf[r * KP + k0 + tg]);
            qf[ks][1] = fu(sbuf[(r + 8) * KP + k0 + tg]);
            qf[ks][2] = fu(sbuf[r * KP + k0 + tg + 4]);
            qf[ks][3] = fu(sbuf[(r + 8) * KP + k0 + tg + 4]);
        }
    }
    __syncthreads();

    float o[8][4];
#pragma unroll
    for (int nt = 0; nt < 8; nt++)
#pragma unroll
        for (int i = 0; i < 4; i++) o[nt][i] = 0.f;

    float m0 = -INFINITY, m1 = -INFINITY, l0 = 0.f, l1 = 0.f;
    const int ig0 = q_base + w * 16 + gr;
    const int ig1 = ig0 + 8;
    const int src0 = (lane & ~3) | (tg >> 1);   // P-permute source lanes
    const int src2 = src0 + 2;
    const unsigned FULL = 0xffffffffu;

    const int nkt = 2 * qt + 2;
    for (int kt = 0; kt < nkt; kt++) {
        // ---- load K,V tiles [32 keys x 64 d], tf32-rounded ----
#pragma unroll
        for (int i = 0; i < 4; i++) {
            int idx = tid + i * 128;
            int row = idx >> 4, dq = idx & 15;
            size_t g = base_bn + (size_t)(kt * 32 + row) * EMB + dq * 4;
            float4 kk = *(const float4*)(k + g);
            kk.x = tf32r(kk.x); kk.y = tf32r(kk.y);
            kk.z = tf32r(kk.z); kk.w = tf32r(kk.w);
            *(float4*)&Ks[row * KP + dq * 4] = kk;
            float4 vv = *(const float4*)(v + g);
            vv.x = tf32r(vv.x); vv.y = tf32r(vv.y);
            vv.z = tf32r(vv.z); vv.w = tf32r(vv.w);
            *(float4*)&Vs[row * VP + dq * 4] = vv;
        }
        __syncthreads();

        // ---- scores: S[16 rows x 32 keys] per warp (Q frags in regs) ----
        float sc[4][4];
#pragma unroll
        for (int nt = 0; nt < 4; nt++)
#pragma unroll
            for (int i = 0; i < 4; i++) sc[nt][i] = 0.f;
#pragma unroll
        for (int ks = 0; ks < 8; ks++) {
            const int k0 = ks * 8;
            uint32_t bf[4][2];
#pragma unroll
            for (int nt = 0; nt < 4; nt++) {
                int c = nt * 8 + gr;
                bf[nt][0] = fu(Ks[c * KP + k0 + tg]);
                bf[nt][1] = fu(Ks[c * KP + k0 + tg + 4]);
            }
#pragma unroll
            for (int nt = 0; nt < 4; nt++)
                mma_tf32(sc[nt], qf[ks], bf[nt]);
        }

        // ---- causal mask (register-side) ----
        if (kt >= 2 * qt) {
            const int jb = kt * 32 + tg * 2;
#pragma unroll
            for (int nt = 0; nt < 4; nt++) {
                int jg = jb + nt * 8;
                if (jg > ig0)     sc[nt][0] = -1e30f;
                if (jg + 1 > ig0) sc[nt][1] = -1e30f;
                if (jg > ig1)     sc[nt][2] = -1e30f;
                if (jg + 1 > ig1) sc[nt][3] = -1e30f;
            }
        }

        // ---- row max (local + bfly over tg lanes) ----
        float tm0 = sc[0][0], tm1 = sc[0][2];
#pragma unroll
        for (int nt = 0; nt < 4; nt++) {
            tm0 = fmaxf(tm0, fmaxf(sc[nt][0], sc[nt][1]));
            tm1 = fmaxf(tm1, fmaxf(sc[nt][2], sc[nt][3]));
        }
        tm0 = fmaxf(tm0, __shfl_xor_sync(FULL, tm0, 1));
        tm0 = fmaxf(tm0, __shfl_xor_sync(FULL, tm0, 2));
        tm1 = fmaxf(tm1, __shfl_xor_sync(FULL, tm1, 1));
        tm1 = fmaxf(tm1, __shfl_xor_sync(FULL, tm1, 2));

        float mn0 = fmaxf(m0, tm0), mn1 = fmaxf(m1, tm1);
        float a0 = __expf(m0 - mn0), a1 = __expf(m1 - mn1);  // exp(-inf)=0
        m0 = mn0; m1 = mn1;

        // ---- exp + row sum; P as tf32 bits ----
        uint32_t u[4][4];
        float s0 = 0.f, s1 = 0.f;
#pragma unroll
        for (int nt = 0; nt < 4; nt++) {
            float p00 = __expf(sc[nt][0] - mn0);
            float p01 = __expf(sc[nt][1] - mn0);
            float p10 = __expf(sc[nt][2] - mn1);
            float p11 = __expf(sc[nt][3] - mn1);
            s0 += p00 + p01; s1 += p10 + p11;
            u[nt][0] = tf32u(p00); u[nt][1] = tf32u(p01);
            u[nt][2] = tf32u(p10); u[nt][3] = tf32u(p11);
        }
        s0 += __shfl_xor_sync(FULL, s0, 1);
        s0 += __shfl_xor_sync(FULL, s0, 2);
        s1 += __shfl_xor_sync(FULL, s1, 1);
        s1 += __shfl_xor_sync(FULL, s1, 2);
        l0 = l0 * a0 + s0;
        l1 = l1 * a1 + s1;

        // ---- rescale O ----
#pragma unroll
        for (int nt = 0; nt < 8; nt++) {
            o[nt][0] *= a0; o[nt][1] *= a0;
            o[nt][2] *= a1; o[nt][3] *= a1;
        }

        // ---- O += P @ V : permute P C-frag -> A-frag via shuffles ----
#pragma unroll
        for (int ks = 0; ks < 4; ks++) {
            uint32_t af[4];
            uint32_t e0 = __shfl_sync(FULL, u[ks][0], src0);
            uint32_t e1 = __shfl_sync(FULL, u[ks][1], src0);
            af[0] = (tg & 1) ? e1 : e0;
            uint32_t f0 = __shfl_sync(FULL, u[ks][2], src0);
            uint32_t f1 = __shfl_sync(FULL, u[ks][3], src0);
            af[1] = (tg & 1) ? f1 : f0;
            uint32_t g0 = __shfl_sync(FULL, u[ks][0], src2);
            uint32_t g1 = __shfl_sync(FULL, u[ks][1], src2);
            af[2] = (tg & 1) ? g1 : g0;
            uint32_t h0 = __shfl_sync(FULL, u[ks][2], src2);
            uint32_t h1 = __shfl_sync(FULL, u[ks][3], src2);
            af[3] = (tg & 1) ? h1 : h0;
            const int kr = ks * 8 + tg;
#pragma unroll
            for (int nt = 0; nt < 8; nt++) {
                uint32_t bb[2];
                bb[0] = fu(Vs[kr * VP + nt * 8 + gr]);
                bb[1] = fu(Vs[(kr + 4) * VP + nt * 8 + gr]);
                mma_tf32(o[nt], af, bb);
            }
        }
        __syncthreads();   // before next tile overwrites Ks/Vs
    }

    // ---- normalize & store ----
    const float inv0 = 1.f / l0, inv1 = 1.f / l1;
    const int r0 = q_base + w * 16 + gr;
#pragma unroll
    for (int nt = 0; nt < 8; nt++) {
        int d = nt * 8 + tg * 2;
        size_t g0 = base_bn + (size_t)r0 * EMB + d;
        size_t g1 = base_bn + (size_t)(r0 + 8) * EMB + d;
        *(float2*)(z + g0) = make_float2(o[nt][0] * inv0, o[nt][1] * inv0);
        *(float2*)(z + g1) = make_float2(o[nt][2] * inv1, o[nt][3] * inv1);
    }
}

// ---------------------------------------------------------------------------
extern "C" void kernel_launch(void* const* d_in, const int* in_sizes, int n_in,
                              void* d_out, int out_size)
{
    const float* x  = (const float*)d_in[0];
    const float* WQ = (const float*)d_in[1];
    const float* WK = (const float*)d_in[2];
    const float* WV = (const float*)d_in[3];
    const float* WO = (const float*)d_in[4];
    const float* bQ = (const float*)d_in[5];
    const float* bK = (const float*)d_in[6];
    const float* bV = (const float*)d_in[7];
    const float* bO = (const float*)d_in[8];
    float* out = (float*)d_out;

    float *qp, *kp, *vp, *zp;
    cudaGetSymbolAddress((void**)&qp, g_q);
    cudaGetSymbolAddress((void**)&kp, g_k);
    cudaGetSymbolAddress((void**)&vp, g_v);
    cudaGetSymbolAddress((void**)&zp, g_z);

    dim3 ggrid(EMB / 128, BS_TOT / 128);   // 6 x 128
    gemm_tc<true><<<ggrid, 256, GEMM_SMEM>>>(x, WQ, bQ, qp, BS_TOT, EMB, EMB);
    gemm_tc<true><<<ggrid, 256, GEMM_SMEM>>>(x, WK, bK, kp, BS_TOT, EMB, EMB);
    gemm_tc<true><<<ggrid, 256, GEMM_SMEM>>>(x, WV, bV, vp, BS_TOT, EMB, EMB);

    attn_tc<<<dim3(SEQ / 64, NHEADS, BATCH), 128>>>(qp, kp, vp, zp);

    gemm_tc<false><<<ggrid, 256, GEMM_SMEM>>>(zp, WO, bO, out, BS_TOT, EMB, EMB);
}

// round 6
// speedup vs baseline: 4.5415x; 1.0335x over previous
#include <cuda_runtime.h>
#include <math.h>
#include <cstdint>

#define BATCH   8
#define SEQ     2048
#define EMB     768
#define NHEADS  12
#define HDIM    64
#define BS_TOT  (BATCH * SEQ)      // 16384

// Scratch (alloc-free rules): q, k, v, z each [BS_TOT, EMB] fp32
__device__ float g_q[BS_TOT * EMB];
__device__ float g_k[BS_TOT * EMB];
__device__ float g_v[BS_TOT * EMB];
__device__ float g_z[BS_TOT * EMB];

// ===========================================================================
// Helpers: tf32 rounding + m16n8k8 tf32 MMA (sm_80+ baseline PTX; tcgen05 is
// unavailable on the compute_103 non-'a' target this harness uses).
// ===========================================================================
__device__ __forceinline__ float tf32r(float x) {
    uint32_t u;
    asm("cvt.rna.tf32.f32 %0, %1;" : "=r"(u) : "f"(x));
    return __uint_as_float(u);
}
__device__ __forceinline__ uint32_t fu(float x) { return __float_as_uint(x); }
__device__ __forceinline__ uint32_t tf32u(float x) {
    uint32_t u;
    asm("cvt.rna.tf32.f32 %0, %1;" : "=r"(u) : "f"(x));
    return u;
}

// D += A(16x8,row) * B(8x8,col).  acc in fp32.
__device__ __forceinline__ void mma_tf32(float* d, const uint32_t* a,
                                         const uint32_t* b) {
    asm volatile(
        "mma.sync.aligned.m16n8k8.row.col.f32.tf32.tf32.f32 "
        "{%0,%1,%2,%3}, {%4,%5,%6,%7}, {%8,%9}, {%0,%1,%2,%3};"
        : "+f"(d[0]), "+f"(d[1]), "+f"(d[2]), "+f"(d[3])
        : "r"(a[0]), "r"(a[1]), "r"(a[2]), "r"(a[3]),
          "r"(b[0]), "r"(b[1]));
}

// ===========================================================================
// tf32 tensor-core GEMM: C[M,N] = A[M,K] @ B + bias
// QKV=true : B layout [N/64][K][64]  (W_{Q,K,V} [n][e][h], H=64)
// QKV=false: B layout [K][N] row-major (W_O reshaped)
// CTA tile 128x128, BK=32, 256 threads (8 warps x 64x32).
// DOUBLE-BUFFERED smem, ONE sync per k-stage.
// ===========================================================================
#define GP   36
#define NST  (EMB / 32)   // 24
#define GEMM_SMEM (4 * 128 * GP * 4)   // 73728 B (2 bufs x (A+B))

template <bool QKV>
__global__ __launch_bounds__(256) void gemm_tc(
    const float* __restrict__ A, const float* __restrict__ Bm,
    const float* __restrict__ bias, float* __restrict__ C,
    int M, int N, int K)
{
    extern __shared__ float sm[];

    const int tid = threadIdx.x;
    const int wid = tid >> 5, lane = tid & 31;
    const int wr = wid >> 2, wc = wid & 3;
    const int gr = lane >> 2, tg = lane & 3;
    const int m0 = blockIdx.y * 128, n0 = blockIdx.x * 128;

    float acc[4][4][4];
#pragma unroll
    for (int mt = 0; mt < 4; mt++)
#pragma unroll
        for (int nt = 0; nt < 4; nt++)
#pragma unroll
            for (int i = 0; i < 4; i++) acc[mt][nt][i] = 0.f;

    float4 pa[4], pb[4];

    auto loadG = [&](int s) {
        const int k0 = s * 32;
#pragma unroll
        for (int i = 0; i < 4; i++) {
            int idx = tid + i * 256;
            int row = idx >> 3, kq = idx & 7;
            pa[i] = *(const float4*)(A + (size_t)(m0 + row) * K + k0 + kq * 4);
        }
#pragma unroll
        for (int i = 0; i < 4; i++) {
            int idx = tid + i * 256;
            int row = idx & 127, kq = idx >> 7;
            int nn = n0 + row, kk = k0 + kq * 4;
            float4 v;
            if (QKV) {
                const float* bp = Bm + ((size_t)(nn >> 6) * K + kk) * 64 + (nn & 63);
                v.x = bp[0]; v.y = bp[64]; v.z = bp[128]; v.w = bp[192];
            } else {
                const float* bp = Bm + (size_t)kk * N + nn;
                v.x = bp[0]; v.y = bp[N]; v.z = bp[2 * N]; v.w = bp[3 * N];
            }
            pb[i] = v;
        }
    };
    auto r2s = [&](int buf) {
        float* As = sm + buf * (2 * 128 * GP);
        float* Bs = As + 128 * GP;
#pragma unroll
        for (int i = 0; i < 4; i++) {
            int idx = tid + i * 256;
            int row = idx >> 3, kq = idx & 7;
            float4 v = pa[i];
            v.x = tf32r(v.x); v.y = tf32r(v.y);
            v.z = tf32r(v.z); v.w = tf32r(v.w);
            *(float4*)&As[row * GP + kq * 4] = v;
        }
#pragma unroll
        for (int i = 0; i < 4; i++) {
            int idx = tid + i * 256;
            int row = idx & 127, kq = idx >> 7;
            float4 v = pb[i];
            v.x = tf32r(v.x); v.y = tf32r(v.y);
            v.z = tf32r(v.z); v.w = tf32r(v.w);
            *(float4*)&Bs[row * GP + kq * 4] = v;
        }
    };

    loadG(0);
    r2s(0);

    for (int s = 0; s < NST; s++) {
        __syncthreads();   // separates {compute(s-1), r2s(s)} from {compute(s), r2s(s+1)}
        if (s + 1 < NST) loadG(s + 1);

        const float* As = sm + (s & 1) * (2 * 128 * GP);
        const float* Bs = As + 128 * GP;
#pragma unroll
        for (int ks = 0; ks < 4; ks++) {
            const int k0 = ks * 8;
            uint32_t af[4][4], bf[4][2];
#pragma unroll
            for (int mt = 0; mt < 4; mt++) {
                int r = wr * 64 + mt * 16 + gr;
                af[mt][0] = fu(As[r * GP + k0 + tg]);
                af[mt][1] = fu(As[(r + 8) * GP + k0 + tg]);
                af[mt][2] = fu(As[r * GP + k0 + tg + 4]);
                af[mt][3] = fu(As[(r + 8) * GP + k0 + tg + 4]);
            }
#pragma unroll
            for (int nt = 0; nt < 4; nt++) {
                int c = wc * 32 + nt * 8 + gr;
                bf[nt][0] = fu(Bs[c * GP + k0 + tg]);
                bf[nt][1] = fu(Bs[c * GP + k0 + tg + 4]);
            }
#pragma unroll
            for (int mt = 0; mt < 4; mt++)
#pragma unroll
                for (int nt = 0; nt < 4; nt++)
                    mma_tf32(acc[mt][nt], af[mt], bf[nt]);
        }
        if (s + 1 < NST) r2s((s + 1) & 1);
    }

#pragma unroll
    for (int mt = 0; mt < 4; mt++)
#pragma unroll
        for (int nt = 0; nt < 4; nt++) {
            int r = m0 + wr * 64 + mt * 16 + gr;
            int c = n0 + wc * 32 + nt * 8 + tg * 2;
            float b0 = bias[c], b1 = bias[c + 1];
            float2 v0 = make_float2(acc[mt][nt][0] + b0, acc[mt][nt][1] + b1);
            float2 v1 = make_float2(acc[mt][nt][2] + b0, acc[mt][nt][3] + b1);
            *(float2*)(C + (size_t)r * N + c) = v0;
            *(float2*)(C + (size_t)(r + 8) * N + c) = v1;
        }
}

// ===========================================================================
// Flash attention (causal), tf32 MMA, register-resident online softmax.
// One block = (b, head, 128-query tile); key tiles of 32; 128 threads, 4 warps.
// Warp w owns query rows [32w, 32w+32) -> TWO 16-row m-tiles, so every K/V
// fragment load is shared by 2 MMAs (LDS/MMA ratio 1.0 vs 2.0 before).
// Ks pitch 68 (conflict-free K frags), Vs pitch 72 (conflict-free V frags).
// ===========================================================================
#define KP 68
#define VP 72

__global__ __launch_bounds__(128) void attn_tc(
    const float* __restrict__ q, const float* __restrict__ k,
    const float* __restrict__ v, float* __restrict__ z)
{
    __shared__ float sbuf[128 * KP];   // 34.8 KB; Q staging aliases K/V space
    float* Ks = sbuf;
    float* Vs = sbuf + 32 * KP;

    const int tid = threadIdx.x;
    const int w = tid >> 5, lane = tid & 31;
    const int gr = lane >> 2, tg = lane & 3;
    const int qt = blockIdx.x, hn = blockIdx.y, b = blockIdx.z;
    const int q_base = qt * 128;
    const size_t base_bn = (size_t)b * SEQ * EMB + (size_t)hn * HDIM;

    // ---- Q phase: gmem -> smem[128][68] -> register fragments ----
#pragma unroll
    for (int i = 0; i < 16; i++) {
        int idx = tid + i * 128;
        int row = idx >> 4, dq = idx & 15;
        float4 x = *(const float4*)(q + base_bn + (size_t)(q_base + row) * EMB + dq * 4);
        x.x = tf32r(x.x * 0.125f); x.y = tf32r(x.y * 0.125f);
        x.z = tf32r(x.z * 0.125f); x.w = tf32r(x.w * 0.125f);
        *(float4*)&sbuf[row * KP + dq * 4] = x;
    }
    __syncthreads();
    uint32_t qf[2][8][4];
#pragma unroll
    for (int mt = 0; mt < 2; mt++) {
        const int r = w * 32 + mt * 16 + gr;
#pragma unroll
        for (int ks = 0; ks < 8; ks++) {
            int k0 = ks * 8;
            qf[mt][ks][0] = fu(sbuf[r * KP + k0 + tg]);
            qf[mt][ks][1] = fu(sbuf[(r + 8) * KP + k0 + tg]);
            qf[mt][ks][2] = fu(sbuf[r * KP + k0 + tg + 4]);
            qf[mt][ks][3] = fu(sbuf[(r + 8) * KP + k0 + tg + 4]);
        }
    }
    __syncthreads();

    float o[2][8][4];
#pragma unroll
    for (int mt = 0; mt < 2; mt++)
#pragma unroll
        for (int nt = 0; nt < 8; nt++)
#pragma unroll
            for (int i = 0; i < 4; i++) o[mt][nt][i] = 0.f;

    float mX[2][2] = {{-INFINITY, -INFINITY}, {-INFINITY, -INFINITY}};
    float lX[2][2] = {{0.f, 0.f}, {0.f, 0.f}};

    const int wrow = q_base + w * 32;          // warp's first query row
    const int src0 = (lane & ~3) | (tg >> 1);  // P-permute source lanes
    const int src2 = src0 + 2;
    const unsigned FULL = 0xffffffffu;

    const int nkt = 4 * qt + 4;
    for (int kt = 0; kt < nkt; kt++) {
        // ---- cooperative load K,V tiles [32 keys x 64 d], tf32-rounded ----
#pragma unroll
        for (int i = 0; i < 4; i++) {
            int idx = tid + i * 128;
            int row = idx >> 4, dq = idx & 15;
            size_t g = base_bn + (size_t)(kt * 32 + row) * EMB + dq * 4;
            float4 kk = *(const float4*)(k + g);
            kk.x = tf32r(kk.x); kk.y = tf32r(kk.y);
            kk.z = tf32r(kk.z); kk.w = tf32r(kk.w);
            *(float4*)&Ks[row * KP + dq * 4] = kk;
            float4 vv = *(const float4*)(v + g);
            vv.x = tf32r(vv.x); vv.y = tf32r(vv.y);
            vv.z = tf32r(vv.z); vv.w = tf32r(vv.w);
            *(float4*)&Vs[row * VP + dq * 4] = vv;
        }
        __syncthreads();

        // warp-uniform skip: tile entirely above the causal diagonal
        if (kt * 32 <= wrow + 31) {
            // ---- scores: S[2 x 16 rows x 32 keys]; bf shared across mt ----
            float sc[2][4][4];
#pragma unroll
            for (int mt = 0; mt < 2; mt++)
#pragma unroll
                for (int nt = 0; nt < 4; nt++)
#pragma unroll
                    for (int i = 0; i < 4; i++) sc[mt][nt][i] = 0.f;
#pragma unroll
            for (int ks = 0; ks < 8; ks++) {
                const int k0 = ks * 8;
                uint32_t bf[4][2];
#pragma unroll
                for (int nt = 0; nt < 4; nt++) {
                    int c = nt * 8 + gr;
                    bf[nt][0] = fu(Ks[c * KP + k0 + tg]);
                    bf[nt][1] = fu(Ks[c * KP + k0 + tg + 4]);
                }
#pragma unroll
                for (int nt = 0; nt < 4; nt++) {
                    mma_tf32(sc[0][nt], qf[0][ks], bf[nt]);
                    mma_tf32(sc[1][nt], qf[1][ks], bf[nt]);
                }
            }

            // ---- causal mask (only tiles overlapping the diagonal) ----
            if (kt * 32 + 31 > wrow) {
#pragma unroll
                for (int mt = 0; mt < 2; mt++) {
                    const int ig0 = wrow + mt * 16 + gr;
                    const int ig1 = ig0 + 8;
                    const int jb = kt * 32 + tg * 2;
#pragma unroll
                    for (int nt = 0; nt < 4; nt++) {
                        int jg = jb + nt * 8;
                        if (jg > ig0)     sc[mt][nt][0] = -1e30f;
                        if (jg + 1 > ig0) sc[mt][nt][1] = -1e30f;
                        if (jg > ig1)     sc[mt][nt][2] = -1e30f;
                        if (jg + 1 > ig1) sc[mt][nt][3] = -1e30f;
                    }
                }
            }

            // ---- online softmax per m-tile (bfly reduces over tg lanes) ----
            float aa[2][2];
#pragma unroll
            for (int mt = 0; mt < 2; mt++) {
                float tm0 = sc[mt][0][0], tm1 = sc[mt][0][2];
#pragma unroll
                for (int nt = 0; nt < 4; nt++) {
                    tm0 = fmaxf(tm0, fmaxf(sc[mt][nt][0], sc[mt][nt][1]));
                    tm1 = fmaxf(tm1, fmaxf(sc[mt][nt][2], sc[mt][nt][3]));
                }
                tm0 = fmaxf(tm0, __shfl_xor_sync(FULL, tm0, 1));
                tm0 = fmaxf(tm0, __shfl_xor_sync(FULL, tm0, 2));
                tm1 = fmaxf(tm1, __shfl_xor_sync(FULL, tm1, 1));
                tm1 = fmaxf(tm1, __shfl_xor_sync(FULL, tm1, 2));

                float mn0 = fmaxf(mX[mt][0], tm0), mn1 = fmaxf(mX[mt][1], tm1);
                float a0 = __expf(mX[mt][0] - mn0), a1 = __expf(mX[mt][1] - mn1);
                mX[mt][0] = mn0; mX[mt][1] = mn1;

                float s0 = 0.f, s1 = 0.f;
#pragma unroll
                for (int nt = 0; nt < 4; nt++) {
                    float p00 = __expf(sc[mt][nt][0] - mn0);
                    float p01 = __expf(sc[mt][nt][1] - mn0);
                    float p10 = __expf(sc[mt][nt][2] - mn1);
                    float p11 = __expf(sc[mt][nt][3] - mn1);
                    s0 += p00 + p01; s1 += p10 + p11;
                    sc[mt][nt][0] = p00; sc[mt][nt][1] = p01;
                    sc[mt][nt][2] = p10; sc[mt][nt][3] = p11;
                }
                s0 += __shfl_xor_sync(FULL, s0, 1);
                s0 += __shfl_xor_sync(FULL, s0, 2);
                s1 += __shfl_xor_sync(FULL, s1, 1);
                s1 += __shfl_xor_sync(FULL, s1, 2);
                lX[mt][0] = lX[mt][0] * a0 + s0;
                lX[mt][1] = lX[mt][1] * a1 + s1;
                aa[mt][0] = a0; aa[mt][1] = a1;
            }

            // ---- rescale O ----
#pragma unroll
            for (int mt = 0; mt < 2; mt++)
#pragma unroll
                for (int nt = 0; nt < 8; nt++) {
                    o[mt][nt][0] *= aa[mt][0]; o[mt][nt][1] *= aa[mt][0];
                    o[mt][nt][2] *= aa[mt][1]; o[mt][nt][3] *= aa[mt][1];
                }

            // ---- O += P @ V : shuffle P to A-frag layout; bb shared by mt --
#pragma unroll
            for (int kg = 0; kg < 4; kg++) {
                uint32_t af[2][4];
#pragma unroll
                for (int mt = 0; mt < 2; mt++) {
                    float e0 = __shfl_sync(FULL, sc[mt][kg][0], src0);
                    float e1 = __shfl_sync(FULL, sc[mt][kg][1], src0);
                    af[mt][0] = tf32u((tg & 1) ? e1 : e0);
                    float f0 = __shfl_sync(FULL, sc[mt][kg][2], src0);
                    float f1 = __shfl_sync(FULL, sc[mt][kg][3], src0);
                    af[mt][1] = tf32u((tg & 1) ? f1 : f0);
                    float g0 = __shfl_sync(FULL, sc[mt][kg][0], src2);
                    float g1 = __shfl_sync(FULL, sc[mt][kg][1], src2);
                    af[mt][2] = tf32u((tg & 1) ? g1 : g0);
                    float h0 = __shfl_sync(FULL, sc[mt][kg][2], src2);
                    float h1 = __shfl_sync(FULL, sc[mt][kg][3], src2);
                    af[mt][3] = tf32u((tg & 1) ? h1 : h0);
                }
                const int kr = kg * 8 + tg;
#pragma unroll
                for (int nt = 0; nt < 8; nt++) {
                    uint32_t bb[2];
                    bb[0] = fu(Vs[kr * VP + nt * 8 + gr]);
                    bb[1] = fu(Vs[(kr + 4) * VP + nt * 8 + gr]);
                    mma_tf32(o[0][nt], af[0], bb);
                    mma_tf32(o[1][nt], af[1], bb);
                }
            }
        }
        __syncthreads();   // before next tile overwrites Ks/Vs
    }

    // ---- normalize & store ----
#pragma unroll
    for (int mt = 0; mt < 2; mt++) {
        const float inv0 = 1.f / lX[mt][0], inv1 = 1.f / lX[mt][1];
        const int r0 = wrow + mt * 16 + gr;
#pragma unroll
        for (int nt = 0; nt < 8; nt++) {
            int d = nt * 8 + tg * 2;
            size_t g0 = base_bn + (size_t)r0 * EMB + d;
            size_t g1 = base_bn + (size_t)(r0 + 8) * EMB + d;
            *(float2*)(z + g0) = make_float2(o[mt][nt][0] * inv0, o[mt][nt][1] * inv0);
            *(float2*)(z + g1) = make_float2(o[mt][nt][2] * inv1, o[mt][nt][3] * inv1);
        }
    }
}

// ---------------------------------------------------------------------------
extern "C" void kernel_launch(void* const* d_in, const int* in_sizes, int n_in,
                              void* d_out, int out_size)
{
    const float* x  = (const float*)d_in[0];
    const float* WQ = (const float*)d_in[1];
    const float* WK = (const float*)d_in[2];
    const float* WV = (const float*)d_in[3];
    const float* WO = (const float*)d_in[4];
    const float* bQ = (const float*)d_in[5];
    const float* bK = (const float*)d_in[6];
    const float* bV = (const float*)d_in[7];
    const float* bO = (const float*)d_in[8];
    float* out = (float*)d_out;

    float *qp, *kp, *vp, *zp;
    cudaGetSymbolAddress((void**)&qp, g_q);
    cudaGetSymbolAddress((void**)&kp, g_k);
    cudaGetSymbolAddress((void**)&vp, g_v);
    cudaGetSymbolAddress((void**)&zp, g_z);

    // Idempotent opt-in for 72KB dynamic smem (host-side, capture-legal).
    cudaFuncSetAttribute(gemm_tc<true>,
        cudaFuncAttributeMaxDynamicSharedMemorySize, GEMM_SMEM);
    cudaFuncSetAttribute(gemm_tc<false>,
        cudaFuncAttributeMaxDynamicSharedMemorySize, GEMM_SMEM);

    dim3 ggrid(EMB / 128, BS_TOT / 128);   // 6 x 128
    gemm_tc<true><<<ggrid, 256, GEMM_SMEM>>>(x, WQ, bQ, qp, BS_TOT, EMB, EMB);
    gemm_tc<true><<<ggrid, 256, GEMM_SMEM>>>(x, WK, bK, kp, BS_TOT, EMB, EMB);
    gemm_tc<true><<<ggrid, 256, GEMM_SMEM>>>(x, WV, bV, vp, BS_TOT, EMB, EMB);

    attn_tc<<<dim3(SEQ / 128, NHEADS, BATCH), 128>>>(qp, kp, vp, zp);

    gemm_tc<false><<<ggrid, 256, GEMM_SMEM>>>(zp, WO, bO, out, BS_TOT, EMB, EMB);
}

// round 7
// speedup vs baseline: 7.4584x; 1.6423x over previous
#include <cuda_runtime.h>
#include <cuda_fp16.h>
#include <math.h>
#include <cstdint>

#define BATCH   8
#define SEQ     2048
#define EMB     768
#define NHEADS  12
#define HDIM    64
#define BS_TOT  (BATCH * SEQ)      // 16384

// Scratch (alloc-free rules): q, k, v, z each [BS_TOT, EMB] fp32
__device__ float g_q[BS_TOT * EMB];
__device__ float g_k[BS_TOT * EMB];
__device__ float g_v[BS_TOT * EMB];
__device__ float g_z[BS_TOT * EMB];

// ===========================================================================
// Helpers: fp16 m16n8k16 MMA (fp32 accum), half2 packing, ldmatrix.trans.
// (tcgen05 unavailable on the compute_103 non-'a' target this harness uses.)
// ===========================================================================
__device__ __forceinline__ uint32_t packh2(float lo, float hi) {
    __half2 h = __floats2half2_rn(lo, hi);
    return *(uint32_t*)&h;
}

// D += A(16x16,row) * B(16x8,col).  A: 4 b32 (half2), B: 2 b32, acc fp32.
__device__ __forceinline__ void mma_f16(float* d, const uint32_t* a,
                                        const uint32_t* b) {
    asm volatile(
        "mma.sync.aligned.m16n8k16.row.col.f32.f16.f16.f32 "
        "{%0,%1,%2,%3}, {%4,%5,%6,%7}, {%8,%9}, {%0,%1,%2,%3};"
        : "+f"(d[0]), "+f"(d[1]), "+f"(d[2]), "+f"(d[3])
        : "r"(a[0]), "r"(a[1]), "r"(a[2]), "r"(a[3]),
          "r"(b[0]), "r"(b[1]));
}

__device__ __forceinline__ void ldmatrix_x4_trans(uint32_t* r, uint32_t addr) {
    asm volatile(
        "ldmatrix.sync.aligned.m8n8.x4.trans.shared.b16 {%0,%1,%2,%3}, [%4];"
        : "=r"(r[0]), "=r"(r[1]), "=r"(r[2]), "=r"(r[3]) : "r"(addr));
}

__device__ __forceinline__ uint32_t smem_u32(const void* p) {
    uint32_t a;
    asm("{ .reg .u64 t; cvta.to.shared.u64 t, %1; cvt.u32.u64 %0, t; }"
        : "=r"(a) : "l"(p));
    return a;
}

// ===========================================================================
// fp16 tensor-core GEMM: C[M,N] = A[M,K] @ B + bias
// QKV=true : B layout [N/64][K][64]  (W_{Q,K,V} [n][e][h], H=64)
// QKV=false: B layout [K][N] row-major (W_O reshaped)
// CTA tile 128x128, BK=32, 256 threads (8 warps x 64x32), double-buffered,
// one sync per k-stage.  Smem half pitch 40 -> fragment loads conflict-free.
// ===========================================================================
#define GPH  40
#define NST  (EMB / 32)   // 24

template <bool QKV>
__global__ __launch_bounds__(256) void gemm_tc(
    const float* __restrict__ A, const float* __restrict__ Bm,
    const float* __restrict__ bias, float* __restrict__ C,
    int M, int N, int K)
{
    __shared__ __half smh[2][2 * 128 * GPH];   // 40 KB static

    const int tid = threadIdx.x;
    const int wid = tid >> 5, lane = tid & 31;
    const int wr = wid >> 2, wc = wid & 3;
    const int gr = lane >> 2, tg = lane & 3;
    const int m0 = blockIdx.y * 128, n0 = blockIdx.x * 128;

    float acc[4][4][4];
#pragma unroll
    for (int mt = 0; mt < 4; mt++)
#pragma unroll
        for (int nt = 0; nt < 4; nt++)
#pragma unroll
            for (int i = 0; i < 4; i++) acc[mt][nt][i] = 0.f;

    float4 pa[4], pb[4];

    auto loadG = [&](int s) {
        const int k0 = s * 32;
#pragma unroll
        for (int i = 0; i < 4; i++) {
            int idx = tid + i * 256;
            int row = idx >> 3, kq = idx & 7;
            pa[i] = *(const float4*)(A + (size_t)(m0 + row) * K + k0 + kq * 4);
        }
#pragma unroll
        for (int i = 0; i < 4; i++) {
            int idx = tid + i * 256;
            int row = idx & 127, kq = idx >> 7;
            int nn = n0 + row, kk = k0 + kq * 4;
            float4 v;
            if (QKV) {
                const float* bp = Bm + ((size_t)(nn >> 6) * K + kk) * 64 + (nn & 63);
                v.x = bp[0]; v.y = bp[64]; v.z = bp[128]; v.w = bp[192];
            } else {
                const float* bp = Bm + (size_t)kk * N + nn;
                v.x = bp[0]; v.y = bp[N]; v.z = bp[2 * N]; v.w = bp[3 * N];
            }
            pb[i] = v;
        }
    };
    auto r2s = [&](int buf) {
        __half* As = smh[buf];
        __half* Bs = As + 128 * GPH;
#pragma unroll
        for (int i = 0; i < 4; i++) {
            int idx = tid + i * 256;
            int row = idx >> 3, kq = idx & 7;
            uint2 u = make_uint2(packh2(pa[i].x, pa[i].y), packh2(pa[i].z, pa[i].w));
            *(uint2*)&As[row * GPH + kq * 4] = u;
        }
#pragma unroll
        for (int i = 0; i < 4; i++) {
            int idx = tid + i * 256;
            int row = idx & 127, kq = idx >> 7;
            uint2 u = make_uint2(packh2(pb[i].x, pb[i].y), packh2(pb[i].z, pb[i].w));
            *(uint2*)&Bs[row * GPH + kq * 4] = u;
        }
    };

    loadG(0);
    r2s(0);

    for (int s = 0; s < NST; s++) {
        __syncthreads();
        if (s + 1 < NST) loadG(s + 1);

        const __half* As = smh[s & 1];
        const __half* Bs = As + 128 * GPH;
#pragma unroll
        for (int ks = 0; ks < 2; ks++) {        // 2 x k16 per 32-wide stage
            const int k0 = ks * 16;
            uint32_t af[4][4], bf[4][2];
#pragma unroll
            for (int mt = 0; mt < 4; mt++) {
                int r = wr * 64 + mt * 16 + gr;
                af[mt][0] = *(const uint32_t*)&As[r * GPH + k0 + 2 * tg];
                af[mt][1] = *(const uint32_t*)&As[(r + 8) * GPH + k0 + 2 * tg];
                af[mt][2] = *(const uint32_t*)&As[r * GPH + k0 + 8 + 2 * tg];
                af[mt][3] = *(const uint32_t*)&As[(r + 8) * GPH + k0 + 8 + 2 * tg];
            }
#pragma unroll
            for (int nt = 0; nt < 4; nt++) {
                int c = wc * 32 + nt * 8 + gr;
                bf[nt][0] = *(const uint32_t*)&Bs[c * GPH + k0 + 2 * tg];
                bf[nt][1] = *(const uint32_t*)&Bs[c * GPH + k0 + 8 + 2 * tg];
            }
#pragma unroll
            for (int mt = 0; mt < 4; mt++)
#pragma unroll
                for (int nt = 0; nt < 4; nt++)
                    mma_f16(acc[mt][nt], af[mt], bf[nt]);
        }
        if (s + 1 < NST) r2s((s + 1) & 1);
    }

#pragma unroll
    for (int mt = 0; mt < 4; mt++)
#pragma unroll
        for (int nt = 0; nt < 4; nt++) {
            int r = m0 + wr * 64 + mt * 16 + gr;
            int c = n0 + wc * 32 + nt * 8 + tg * 2;
            float b0 = bias[c], b1 = bias[c + 1];
            float2 v0 = make_float2(acc[mt][nt][0] + b0, acc[mt][nt][1] + b1);
            float2 v1 = make_float2(acc[mt][nt][2] + b0, acc[mt][nt][3] + b1);
            *(float2*)(C + (size_t)r * N + c) = v0;
            *(float2*)(C + (size_t)(r + 8) * N + c) = v1;
        }
}

// Fused Q/K/V projection: blockIdx.z selects the weight/bias/output triple.
__global__ __launch_bounds__(256) void gemm_qkv(
    const float* __restrict__ A,
    const float* __restrict__ WQ, const float* __restrict__ WK,
    const float* __restrict__ WV,
    const float* __restrict__ bQ, const float* __restrict__ bK,
    const float* __restrict__ bV,
    float* __restrict__ Cq, float* __restrict__ Ck, float* __restrict__ Cv)
{
    // Dispatch into the shared template body by re-binding pointers.
    const float* Bm  = (blockIdx.z == 0) ? WQ : (blockIdx.z == 1) ? WK : WV;
    const float* bias = (blockIdx.z == 0) ? bQ : (blockIdx.z == 1) ? bK : bV;
    float* C = (blockIdx.z == 0) ? Cq : (blockIdx.z == 1) ? Ck : Cv;

    // --- body identical to gemm_tc<true> ---
    __shared__ __half smh[2][2 * 128 * GPH];
    const int tid = threadIdx.x;
    const int wid = tid >> 5, lane = tid & 31;
    const int wr = wid >> 2, wc = wid & 3;
    const int gr = lane >> 2, tg = lane & 3;
    const int m0 = blockIdx.y * 128, n0 = blockIdx.x * 128;
    const int K = EMB, N = EMB;

    float acc[4][4][4];
#pragma unroll
    for (int mt = 0; mt < 4; mt++)
#pragma unroll
        for (int nt = 0; nt < 4; nt++)
#pragma unroll
            for (int i = 0; i < 4; i++) acc[mt][nt][i] = 0.f;

    float4 pa[4], pb[4];
    auto loadG = [&](int s) {
        const int k0 = s * 32;
#pragma unroll
        for (int i = 0; i < 4; i++) {
            int idx = tid + i * 256;
            int row = idx >> 3, kq = idx & 7;
            pa[i] = *(const float4*)(A + (size_t)(m0 + row) * K + k0 + kq * 4);
        }
#pragma unroll
        for (int i = 0; i < 4; i++) {
            int idx = tid + i * 256;
            int row = idx & 127, kq = idx >> 7;
            int nn = n0 + row, kk = k0 + kq * 4;
            const float* bp = Bm + ((size_t)(nn >> 6) * K + kk) * 64 + (nn & 63);
            pb[i] = make_float4(bp[0], bp[64], bp[128], bp[192]);
        }
    };
    auto r2s = [&](int buf) {
        __half* As = smh[buf];
        __half* Bs = As + 128 * GPH;
#pragma unroll
        for (int i = 0; i < 4; i++) {
            int idx = tid + i * 256;
            int row = idx >> 3, kq = idx & 7;
            uint2 u = make_uint2(packh2(pa[i].x, pa[i].y), packh2(pa[i].z, pa[i].w));
            *(uint2*)&As[row * GPH + kq * 4] = u;
        }
#pragma unroll
        for (int i = 0; i < 4; i++) {
            int idx = tid + i * 256;
            int row = idx & 127, kq = idx >> 7;
            uint2 u = make_uint2(packh2(pb[i].x, pb[i].y), packh2(pb[i].z, pb[i].w));
            *(uint2*)&Bs[row * GPH + kq * 4] = u;
        }
    };

    loadG(0);
    r2s(0);
    for (int s = 0; s < NST; s++) {
        __syncthreads();
        if (s + 1 < NST) loadG(s + 1);
        const __half* As = smh[s & 1];
        const __half* Bs = As + 128 * GPH;
#pragma unroll
        for (int ks = 0; ks < 2; ks++) {
            const int k0 = ks * 16;
            uint32_t af[4][4], bf[4][2];
#pragma unroll
            for (int mt = 0; mt < 4; mt++) {
                int r = wr * 64 + mt * 16 + gr;
                af[mt][0] = *(const uint32_t*)&As[r * GPH + k0 + 2 * tg];
                af[mt][1] = *(const uint32_t*)&As[(r + 8) * GPH + k0 + 2 * tg];
                af[mt][2] = *(const uint32_t*)&As[r * GPH + k0 + 8 + 2 * tg];
                af[mt][3] = *(const uint32_t*)&As[(r + 8) * GPH + k0 + 8 + 2 * tg];
            }
#pragma unroll
            for (int nt = 0; nt < 4; nt++) {
                int c = wc * 32 + nt * 8 + gr;
                bf[nt][0] = *(const uint32_t*)&Bs[c * GPH + k0 + 2 * tg];
                bf[nt][1] = *(const uint32_t*)&Bs[c * GPH + k0 + 8 + 2 * tg];
            }
#pragma unroll
            for (int mt = 0; mt < 4; mt++)
#pragma unroll
                for (int nt = 0; nt < 4; nt++)
                    mma_f16(acc[mt][nt], af[mt], bf[nt]);
        }
        if (s + 1 < NST) r2s((s + 1) & 1);
    }
#pragma unroll
    for (int mt = 0; mt < 4; mt++)
#pragma unroll
        for (int nt = 0; nt < 4; nt++) {
            int r = m0 + wr * 64 + mt * 16 + gr;
            int c = n0 + wc * 32 + nt * 8 + tg * 2;
            float b0 = bias[c], b1 = bias[c + 1];
            float2 v0 = make_float2(acc[mt][nt][0] + b0, acc[mt][nt][1] + b1);
            float2 v1 = make_float2(acc[mt][nt][2] + b0, acc[mt][nt][3] + b1);
            *(float2*)(C + (size_t)r * N + c) = v0;
            *(float2*)(C + (size_t)(r + 8) * N + c) = v1;
        }
}

// ===========================================================================
// Flash attention (causal), fp16 m16n8k16, register-resident online softmax.
// One block = (b, head, 128-query tile); key tiles of 32; 128 threads, 4 warps.
// Warp w owns query rows [32w, 32w+32) = two 16-row m-tiles.
// P score C-frags pack DIRECTLY into fp16 A-frags (no shuffles).
// V consumed via ldmatrix.x4.trans from [key][d] smem.  Half pitch 72.
// ===========================================================================
#define AP 72

__global__ __launch_bounds__(128) void attn_tc(
    const float* __restrict__ q, const float* __restrict__ k,
    const float* __restrict__ v, float* __restrict__ z)
{
    __shared__ __half sbuf[128 * AP];   // 18.4 KB; Q staging aliases K/V
    __half* Ks = sbuf;
    __half* Vs = sbuf + 32 * AP;

    const int tid = threadIdx.x;
    const int w = tid >> 5, lane = tid & 31;
    const int gr = lane >> 2, tg = lane & 3;
    const int qt = blockIdx.x, hn = blockIdx.y, b = blockIdx.z;
    const int q_base = qt * 128;
    const size_t base_bn = (size_t)b * SEQ * EMB + (size_t)hn * HDIM;

    // ---- Q phase: gmem -> smem halves (x1/8) -> A-fragments in regs ----
#pragma unroll
    for (int i = 0; i < 16; i++) {
        int idx = tid + i * 128;
        int row = idx >> 4, dq = idx & 15;
        float4 x = *(const float4*)(q + base_bn + (size_t)(q_base + row) * EMB + dq * 4);
        uint2 u = make_uint2(packh2(x.x * 0.125f, x.y * 0.125f),
                             packh2(x.z * 0.125f, x.w * 0.125f));
        *(uint2*)&sbuf[row * AP + dq * 4] = u;
    }
    __syncthreads();
    uint32_t qf[2][4][4];
#pragma unroll
    for (int mt = 0; mt < 2; mt++) {
        const int r = w * 32 + mt * 16 + gr;
#pragma unroll
        for (int ks = 0; ks < 4; ks++) {
            int k0 = ks * 16;
            qf[mt][ks][0] = *(const uint32_t*)&sbuf[r * AP + k0 + 2 * tg];
            qf[mt][ks][1] = *(const uint32_t*)&sbuf[(r + 8) * AP + k0 + 2 * tg];
            qf[mt][ks][2] = *(const uint32_t*)&sbuf[r * AP + k0 + 8 + 2 * tg];
            qf[mt][ks][3] = *(const uint32_t*)&sbuf[(r + 8) * AP + k0 + 8 + 2 * tg];
        }
    }
    __syncthreads();

    const uint32_t vs_base = smem_u32(Vs);
    // ldmatrix address components (per thread, constant across tiles)
    const int lm_row = ((lane >> 3) & 1) * 8 + (lane & 7);
    const int lm_col = (lane >> 4) * 8;

    float o[2][8][4];
#pragma unroll
    for (int mt = 0; mt < 2; mt++)
#pragma unroll
        for (int nt = 0; nt < 8; nt++)
#pragma unroll
            for (int i = 0; i < 4; i++) o[mt][nt][i] = 0.f;

    float mX[2][2] = {{-INFINITY, -INFINITY}, {-INFINITY, -INFINITY}};
    float lX[2][2] = {{0.f, 0.f}, {0.f, 0.f}};

    const int wrow = q_base + w * 32;
    const int nkt = 4 * qt + 4;

    for (int kt = 0; kt < nkt; kt++) {
        // ---- cooperative load K,V tiles [32 keys x 64 d] as halves ----
#pragma unroll
        for (int i = 0; i < 4; i++) {
            int idx = tid + i * 128;
            int row = idx >> 4, dq = idx & 15;
            size_t g = base_bn + (size_t)(kt * 32 + row) * EMB + dq * 4;
            float4 kk = *(const float4*)(k + g);
            *(uint2*)&Ks[row * AP + dq * 4] =
                make_uint2(packh2(kk.x, kk.y), packh2(kk.z, kk.w));
            float4 vv = *(const float4*)(v + g);
            *(uint2*)&Vs[row * AP + dq * 4] =
                make_uint2(packh2(vv.x, vv.y), packh2(vv.z, vv.w));
        }
        __syncthreads();

        if (kt * 32 <= wrow + 31) {   // warp-uniform causal skip
            // ---- scores: 4 k16-steps over d=64; bf shared across m-tiles ----
            float sc[2][4][4];
#pragma unroll
            for (int mt = 0; mt < 2; mt++)
#pragma unroll
                for (int nt = 0; nt < 4; nt++)
#pragma unroll
                    for (int i = 0; i < 4; i++) sc[mt][nt][i] = 0.f;
#pragma unroll
            for (int ks = 0; ks < 4; ks++) {
                const int k0 = ks * 16;
                uint32_t bf[4][2];
#pragma unroll
                for (int nt = 0; nt < 4; nt++) {
                    int c = nt * 8 + gr;
                    bf[nt][0] = *(const uint32_t*)&Ks[c * AP + k0 + 2 * tg];
                    bf[nt][1] = *(const uint32_t*)&Ks[c * AP + k0 + 8 + 2 * tg];
                }
#pragma unroll
                for (int nt = 0; nt < 4; nt++) {
                    mma_f16(sc[0][nt], qf[0][ks], bf[nt]);
                    mma_f16(sc[1][nt], qf[1][ks], bf[nt]);
                }
            }

            // ---- causal mask (diagonal-overlapping tiles only) ----
            if (kt * 32 + 31 > wrow) {
#pragma unroll
                for (int mt = 0; mt < 2; mt++) {
                    const int ig0 = wrow + mt * 16 + gr;
                    const int ig1 = ig0 + 8;
                    const int jb = kt * 32 + tg * 2;
#pragma unroll
                    for (int nt = 0; nt < 4; nt++) {
                        int jg = jb + nt * 8;
                        if (jg > ig0)     sc[mt][nt][0] = -1e30f;
                        if (jg + 1 > ig0) sc[mt][nt][1] = -1e30f;
                        if (jg > ig1)     sc[mt][nt][2] = -1e30f;
                        if (jg + 1 > ig1) sc[mt][nt][3] = -1e30f;
                    }
                }
            }

            // ---- online softmax per m-tile ----
            const unsigned FULL = 0xffffffffu;
            float aa[2][2];
#pragma unroll
            for (int mt = 0; mt < 2; mt++) {
                float tm0 = sc[mt][0][0], tm1 = sc[mt][0][2];
#pragma unroll
                for (int nt = 0; nt < 4; nt++) {
                    tm0 = fmaxf(tm0, fmaxf(sc[mt][nt][0], sc[mt][nt][1]));
                    tm1 = fmaxf(tm1, fmaxf(sc[mt][nt][2], sc[mt][nt][3]));
                }
                tm0 = fmaxf(tm0, __shfl_xor_sync(FULL, tm0, 1));
                tm0 = fmaxf(tm0, __shfl_xor_sync(FULL, tm0, 2));
                tm1 = fmaxf(tm1, __shfl_xor_sync(FULL, tm1, 1));
                tm1 = fmaxf(tm1, __shfl_xor_sync(FULL, tm1, 2));

                float mn0 = fmaxf(mX[mt][0], tm0), mn1 = fmaxf(mX[mt][1], tm1);
                float a0 = __expf(mX[mt][0] - mn0), a1 = __expf(mX[mt][1] - mn1);
                mX[mt][0] = mn0; mX[mt][1] = mn1;

                float s0 = 0.f, s1 = 0.f;
#pragma unroll
                for (int nt = 0; nt < 4; nt++) {
                    float p00 = __expf(sc[mt][nt][0] - mn0);
                    float p01 = __expf(sc[mt][nt][1] - mn0);
                    float p10 = __expf(sc[mt][nt][2] - mn1);
                    float p11 = __expf(sc[mt][nt][3] - mn1);
                    s0 += p00 + p01; s1 += p10 + p11;
                    sc[mt][nt][0] = p00; sc[mt][nt][1] = p01;
                    sc[mt][nt][2] = p10; sc[mt][nt][3] = p11;
                }
                s0 += __shfl_xor_sync(FULL, s0, 1);
                s0 += __shfl_xor_sync(FULL, s0, 2);
                s1 += __shfl_xor_sync(FULL, s1, 1);
                s1 += __shfl_xor_sync(FULL, s1, 2);
                lX[mt][0] = lX[mt][0] * a0 + s0;
                lX[mt][1] = lX[mt][1] * a1 + s1;
                aa[mt][0] = a0; aa[mt][1] = a1;
            }

            // ---- rescale O ----
#pragma unroll
            for (int mt = 0; mt < 2; mt++)
#pragma unroll
                for (int nt = 0; nt < 8; nt++) {
                    o[mt][nt][0] *= aa[mt][0]; o[mt][nt][1] *= aa[mt][0];
                    o[mt][nt][2] *= aa[mt][1]; o[mt][nt][3] *= aa[mt][1];
                }

            // ---- O += P @ V : P C-frags pack straight into fp16 A-frags ----
#pragma unroll
            for (int kg = 0; kg < 2; kg++) {       // 16 keys per step
                uint32_t af[2][4];
#pragma unroll
                for (int mt = 0; mt < 2; mt++) {
                    af[mt][0] = packh2(sc[mt][2 * kg][0], sc[mt][2 * kg][1]);
                    af[mt][1] = packh2(sc[mt][2 * kg][2], sc[mt][2 * kg][3]);
                    af[mt][2] = packh2(sc[mt][2 * kg + 1][0], sc[mt][2 * kg + 1][1]);
                    af[mt][3] = packh2(sc[mt][2 * kg + 1][2], sc[mt][2 * kg + 1][3]);
                }
                const uint32_t rbase =
                    vs_base + 2 * ((kg * 16 + lm_row) * AP + lm_col);
#pragma unroll
                for (int pr = 0; pr < 4; pr++) {   // d cols pr*16..pr*16+15
                    uint32_t vb[4];
                    ldmatrix_x4_trans(vb, rbase + 2 * (pr * 16));
                    mma_f16(o[0][2 * pr],     af[0], vb);
                    mma_f16(o[0][2 * pr + 1], af[0], vb + 2);
                    mma_f16(o[1][2 * pr],     af[1], vb);
                    mma_f16(o[1][2 * pr + 1], af[1], vb + 2);
                }
            }
        }
        __syncthreads();   // before next tile overwrites Ks/Vs
    }

    // ---- normalize & store ----
#pragma unroll
    for (int mt = 0; mt < 2; mt++) {
        const float inv0 = 1.f / lX[mt][0], inv1 = 1.f / lX[mt][1];
        const int r0 = wrow + mt * 16 + gr;
#pragma unroll
        for (int nt = 0; nt < 8; nt++) {
            int d = nt * 8 + tg * 2;
            size_t g0 = base_bn + (size_t)r0 * EMB + d;
            size_t g1 = base_bn + (size_t)(r0 + 8) * EMB + d;
            *(float2*)(z + g0) = make_float2(o[mt][nt][0] * inv0, o[mt][nt][1] * inv0);
            *(float2*)(z + g1) = make_float2(o[mt][nt][2] * inv1, o[mt][nt][3] * inv1);
        }
    }
}

// ---------------------------------------------------------------------------
extern "C" void kernel_launch(void* const* d_in, const int* in_sizes, int n_in,
                              void* d_out, int out_size)
{
    const float* x  = (const float*)d_in[0];
    const float* WQ = (const float*)d_in[1];
    const float* WK = (const float*)d_in[2];
    const float* WV = (const float*)d_in[3];
    const float* WO = (const float*)d_in[4];
    const float* bQ = (const float*)d_in[5];
    const float* bK = (const float*)d_in[6];
    const float* bV = (const float*)d_in[7];
    const float* bO = (const float*)d_in[8];
    float* out = (float*)d_out;

    float *qp, *kp, *vp, *zp;
    cudaGetSymbolAddress((void**)&qp, g_q);
    cudaGetSymbolAddress((void**)&kp, g_k);
    cudaGetSymbolAddress((void**)&vp, g_v);
    cudaGetSymbolAddress((void**)&zp, g_z);

    // Fused QKV projections: grid (6 n-tiles, 128 m-tiles, 3 matrices)
    gemm_qkv<<<dim3(EMB / 128, BS_TOT / 128, 3), 256>>>(
        x, WQ, WK, WV, bQ, bK, bV, qp, kp, vp);

    attn_tc<<<dim3(SEQ / 128, NHEADS, BATCH), 128>>>(qp, kp, vp, zp);

    gemm_tc<false><<<dim3(EMB / 128, BS_TOT / 128), 256>>>(
        zp, WO, bO, out, BS_TOT, EMB, EMB);
}

// round 9
// speedup vs baseline: 8.3833x; 1.1240x over previous
#include <cuda_runtime.h>
#include <cuda_fp16.h>
#include <math.h>
#include <cstdint>

#define BATCH   8
#define SEQ     2048
#define EMB     768
#define NHEADS  12
#define HDIM    64
#define BS_TOT  (BATCH * SEQ)      // 16384

// Scratch (alloc-free rules): q, k, v, z each [BS_TOT, EMB] __half
__device__ __half g_q[BS_TOT * EMB];
__device__ __half g_k[BS_TOT * EMB];
__device__ __half g_v[BS_TOT * EMB];
__device__ __half g_z[BS_TOT * EMB];

// ===========================================================================
// Helpers (fp16 m16n8k16 mma, ldmatrix; tcgen05 unavailable on compute_103)
// ===========================================================================
__device__ __forceinline__ uint32_t packh2(float lo, float hi) {
    __half2 h = __floats2half2_rn(lo, hi);
    return *(uint32_t*)&h;
}

__device__ __forceinline__ void mma_f16(float* d, const uint32_t* a,
                                        const uint32_t* b) {
    asm volatile(
        "mma.sync.aligned.m16n8k16.row.col.f32.f16.f16.f32 "
        "{%0,%1,%2,%3}, {%4,%5,%6,%7}, {%8,%9}, {%0,%1,%2,%3};"
        : "+f"(d[0]), "+f"(d[1]), "+f"(d[2]), "+f"(d[3])
        : "r"(a[0]), "r"(a[1]), "r"(a[2]), "r"(a[3]),
          "r"(b[0]), "r"(b[1]));
}

__device__ __forceinline__ void ldmatrix_x4(uint32_t* r, uint32_t addr) {
    asm volatile(
        "ldmatrix.sync.aligned.m8n8.x4.shared.b16 {%0,%1,%2,%3}, [%4];"
        : "=r"(r[0]), "=r"(r[1]), "=r"(r[2]), "=r"(r[3]) : "r"(addr));
}
__device__ __forceinline__ void ldmatrix_x4_trans(uint32_t* r, uint32_t addr) {
    asm volatile(
        "ldmatrix.sync.aligned.m8n8.x4.trans.shared.b16 {%0,%1,%2,%3}, [%4];"
        : "=r"(r[0]), "=r"(r[1]), "=r"(r[2]), "=r"(r[3]) : "r"(addr));
}

__device__ __forceinline__ uint32_t smem_u32(const void* p) {
    uint32_t a;
    asm("{ .reg .u64 t; cvta.to.shared.u64 t, %1; cvt.u32.u64 %0, t; }"
        : "=r"(a) : "l"(p));
    return a;
}

#define GPH  40            // smem half pitch (80B = 5x16B; ldmatrix-clean)
#define NST  (EMB / 32)    // 24 k-stages

// ===========================================================================
// Fused QKV projection (A fp32, W [n][e][64] fp32, C half, Q scaled by 1/8).
// CTA 128x128, BK=32, 256 thr (8 warps x 64x32), double-buffered, ldmatrix.
// ===========================================================================
__global__ __launch_bounds__(256) void gemm_qkv(
    const float* __restrict__ A,
    const float* __restrict__ WQ, const float* __restrict__ WK,
    const float* __restrict__ WV,
    const float* __restrict__ bQ, const float* __restrict__ bK,
    const float* __restrict__ bV,
    __half* __restrict__ Cq, __half* __restrict__ Ck, __half* __restrict__ Cv)
{
    const float* Bm   = (blockIdx.z == 0) ? WQ : (blockIdx.z == 1) ? WK : WV;
    const float* bias = (blockIdx.z == 0) ? bQ : (blockIdx.z == 1) ? bK : bV;
    __half* C         = (blockIdx.z == 0) ? Cq : (blockIdx.z == 1) ? Ck : Cv;
    const float qs    = (blockIdx.z == 0) ? 0.125f : 1.0f;

    __shared__ __half smh[2][2 * 128 * GPH];   // 40 KB

    const int tid = threadIdx.x;
    const int wid = tid >> 5, lane = tid & 31;
    const int wr = wid >> 2, wc = wid & 3;
    const int gr = lane >> 2, tg = lane & 3;
    const int m0 = blockIdx.y * 128, n0 = blockIdx.x * 128;
    const int K = EMB, N = EMB;

    // ldmatrix per-lane offsets (in halves)
    const int lmro = (lane & 7) + ((lane >> 3) & 1) * 8;   // A/Q row offset
    const int lmco = (lane >> 4) * 8;                      // A/Q col offset
    const int bid  = lane >> 3;                            // B: matrix id
    const int b_nt = bid >> 1, b_kh = bid & 1;             // B: ntile, khalf
    const int b_ro = (lane & 7);

    float acc[4][4][4];
#pragma unroll
    for (int mt = 0; mt < 4; mt++)
#pragma unroll
        for (int nt = 0; nt < 4; nt++)
#pragma unroll
            for (int i = 0; i < 4; i++) acc[mt][nt][i] = 0.f;

    float4 pa[4], pb[4];
    auto loadG = [&](int s) {
        const int k0 = s * 32;
#pragma unroll
        for (int i = 0; i < 4; i++) {
            int idx = tid + i * 256;
            int row = idx >> 3, kq = idx & 7;
            pa[i] = *(const float4*)(A + (size_t)(m0 + row) * K + k0 + kq * 4);
        }
#pragma unroll
        for (int i = 0; i < 4; i++) {
            int idx = tid + i * 256;
            int row = idx & 127, kq = idx >> 7;
            int nn = n0 + row, kk = k0 + kq * 4;
            const float* bp = Bm + ((size_t)(nn >> 6) * K + kk) * 64 + (nn & 63);
            pb[i] = make_float4(bp[0], bp[64], bp[128], bp[192]);
        }
    };
    auto r2s = [&](int buf) {
        __half* As = smh[buf];
        __half* Bs = As + 128 * GPH;
#pragma unroll
        for (int i = 0; i < 4; i++) {
            int idx = tid + i * 256;
            int row = idx >> 3, kq = idx & 7;
            *(uint2*)&As[row * GPH + kq * 4] =
                make_uint2(packh2(pa[i].x, pa[i].y), packh2(pa[i].z, pa[i].w));
        }
#pragma unroll
        for (int i = 0; i < 4; i++) {
            int idx = tid + i * 256;
            int row = idx & 127, kq = idx >> 7;
            *(uint2*)&Bs[row * GPH + kq * 4] =
                make_uint2(packh2(pb[i].x, pb[i].y), packh2(pb[i].z, pb[i].w));
        }
    };

    loadG(0);
    r2s(0);

    for (int s = 0; s < NST; s++) {
        __syncthreads();
        if (s + 1 < NST) loadG(s + 1);

        const __half* As = smh[s & 1];
        const __half* Bs = As + 128 * GPH;
        const uint32_t a_base =
            smem_u32(As) + 2 * ((wr * 64 + lmro) * GPH + lmco);
        const uint32_t b_base =
            smem_u32(Bs) + 2 * ((wc * 32 + b_nt * 8 + b_ro) * GPH + b_kh * 8);
#pragma unroll
        for (int ks = 0; ks < 2; ks++) {
            const int k0 = ks * 16;
            uint32_t af[4][4], bf[4][2];
#pragma unroll
            for (int mt = 0; mt < 4; mt++)
                ldmatrix_x4(af[mt], a_base + 2 * (mt * 16 * GPH + k0));
#pragma unroll
            for (int p = 0; p < 2; p++) {
                uint32_t r[4];
                ldmatrix_x4(r, b_base + 2 * (p * 16 * GPH + k0));
                bf[2 * p][0] = r[0];     bf[2 * p][1] = r[1];
                bf[2 * p + 1][0] = r[2]; bf[2 * p + 1][1] = r[3];
            }
#pragma unroll
            for (int mt = 0; mt < 4; mt++)
#pragma unroll
                for (int nt = 0; nt < 4; nt++)
                    mma_f16(acc[mt][nt], af[mt], bf[nt]);
        }
        if (s + 1 < NST) r2s((s + 1) & 1);
    }

#pragma unroll
    for (int mt = 0; mt < 4; mt++)
#pragma unroll
        for (int nt = 0; nt < 4; nt++) {
            int r = m0 + wr * 64 + mt * 16 + gr;
            int c = n0 + wc * 32 + nt * 8 + tg * 2;
            float b0 = bias[c], b1 = bias[c + 1];
            *(uint32_t*)&C[(size_t)r * N + c] =
                packh2((acc[mt][nt][0] + b0) * qs, (acc[mt][nt][1] + b1) * qs);
            *(uint32_t*)&C[(size_t)(r + 8) * N + c] =
                packh2((acc[mt][nt][2] + b0) * qs, (acc[mt][nt][3] + b1) * qs);
        }
}

// ===========================================================================
// Output projection: C[M,N] fp32 = A[M,K] (half z) @ WO[K][N] fp32 + bias
// ===========================================================================
__global__ __launch_bounds__(256) void gemm_wo(
    const __half* __restrict__ A, const float* __restrict__ Bm,
    const float* __restrict__ bias, float* __restrict__ C)
{
    __shared__ __half smh[2][2 * 128 * GPH];

    const int tid = threadIdx.x;
    const int wid = tid >> 5, lane = tid & 31;
    const int wr = wid >> 2, wc = wid & 3;
    const int gr = lane >> 2, tg = lane & 3;
    const int m0 = blockIdx.y * 128, n0 = blockIdx.x * 128;
    const int K = EMB, N = EMB;

    const int lmro = (lane & 7) + ((lane >> 3) & 1) * 8;
    const int lmco = (lane >> 4) * 8;
    const int bid  = lane >> 3;
    const int b_nt = bid >> 1, b_kh = bid & 1;
    const int b_ro = (lane & 7);

    float acc[4][4][4];
#pragma unroll
    for (int mt = 0; mt < 4; mt++)
#pragma unroll
        for (int nt = 0; nt < 4; nt++)
#pragma unroll
            for (int i = 0; i < 4; i++) acc[mt][nt][i] = 0.f;

    uint4 pa[2];
    float4 pb[4];
    auto loadG = [&](int s) {
        const int k0 = s * 32;
#pragma unroll
        for (int i = 0; i < 2; i++) {           // A: 128 rows x 4 octets(8h)
            int idx = tid + i * 256;
            int row = idx >> 2, oc = idx & 3;
            pa[i] = *(const uint4*)(A + (size_t)(m0 + row) * K + k0 + oc * 8);
        }
#pragma unroll
        for (int i = 0; i < 4; i++) {
            int idx = tid + i * 256;
            int row = idx & 127, kq = idx >> 7;
            int nn = n0 + row, kk = k0 + kq * 4;
            const float* bp = Bm + (size_t)kk * N + nn;
            pb[i] = make_float4(bp[0], bp[N], bp[2 * N], bp[3 * N]);
        }
    };
    auto r2s = [&](int buf) {
        __half* As = smh[buf];
        __half* Bs = As + 128 * GPH;
#pragma unroll
        for (int i = 0; i < 2; i++) {
            int idx = tid + i * 256;
            int row = idx >> 2, oc = idx & 3;
            *(uint4*)&As[row * GPH + oc * 8] = pa[i];
        }
#pragma unroll
        for (int i = 0; i < 4; i++) {
            int idx = tid + i * 256;
            int row = idx & 127, kq = idx >> 7;
            *(uint2*)&Bs[row * GPH + kq * 4] =
                make_uint2(packh2(pb[i].x, pb[i].y), packh2(pb[i].z, pb[i].w));
        }
    };

    loadG(0);
    r2s(0);

    for (int s = 0; s < NST; s++) {
        __syncthreads();
        if (s + 1 < NST) loadG(s + 1);

        const __half* As = smh[s & 1];
        const __half* Bs = As + 128 * GPH;
        const uint32_t a_base =
            smem_u32(As) + 2 * ((wr * 64 + lmro) * GPH + lmco);
        const uint32_t b_base =
            smem_u32(Bs) + 2 * ((wc * 32 + b_nt * 8 + b_ro) * GPH + b_kh * 8);
#pragma unroll
        for (int ks = 0; ks < 2; ks++) {
            const int k0 = ks * 16;
            uint32_t af[4][4], bf[4][2];
#pragma unroll
            for (int mt = 0; mt < 4; mt++)
                ldmatrix_x4(af[mt], a_base + 2 * (mt * 16 * GPH + k0));
#pragma unroll
            for (int p = 0; p < 2; p++) {
                uint32_t r[4];
                ldmatrix_x4(r, b_base + 2 * (p * 16 * GPH + k0));
                bf[2 * p][0] = r[0];     bf[2 * p][1] = r[1];
                bf[2 * p + 1][0] = r[2]; bf[2 * p + 1][1] = r[3];
            }
#pragma unroll
            for (int mt = 0; mt < 4; mt++)
#pragma unroll
                for (int nt = 0; nt < 4; nt++)
                    mma_f16(acc[mt][nt], af[mt], bf[nt]);
        }
        if (s + 1 < NST) r2s((s + 1) & 1);
    }

#pragma unroll
    for (int mt = 0; mt < 4; mt++)
#pragma unroll
        for (int nt = 0; nt < 4; nt++) {
            int r = m0 + wr * 64 + mt * 16 + gr;
            int c = n0 + wc * 32 + nt * 8 + tg * 2;
            float b0 = bias[c], b1 = bias[c + 1];
            *(float2*)(C + (size_t)r * N + c) =
                make_float2(acc[mt][nt][0] + b0, acc[mt][nt][1] + b1);
            *(float2*)(C + (size_t)(r + 8) * N + c) =
                make_float2(acc[mt][nt][2] + b0, acc[mt][nt][3] + b1);
        }
}

// ===========================================================================
// Flash attention (causal), fp16 m16n8k16, register softmax, all-ldmatrix.
// One block = (b, head, 128-query tile); key tiles of 32; 128 thr, 4 warps.
// q/k/v/z are __half [bs][n*64+d]; Q pre-scaled by 1/8 in projection.
// ===========================================================================
#define AP 72   // half pitch (144B = 9x16B; ldmatrix-clean, conflict-free)

__global__ __launch_bounds__(128) void attn_tc(
    const __half* __restrict__ q, const __half* __restrict__ k,
    const __half* __restrict__ v, __half* __restrict__ z)
{
    __shared__ __half sbuf[128 * AP];   // 18.4 KB; Q staging aliases K/V
    __half* Ks = sbuf;
    __half* Vs = sbuf + 32 * AP;

    const int tid = threadIdx.x;
    const int w = tid >> 5, lane = tid & 31;
    const int gr = lane >> 2, tg = lane & 3;
    const int qt = blockIdx.x, hn = blockIdx.y, b = blockIdx.z;
    const int q_base = qt * 128;
    const size_t base_bn = (size_t)b * SEQ * EMB + (size_t)hn * HDIM;

    const int lmro = (lane & 7) + ((lane >> 3) & 1) * 8;
    const int lmco = (lane >> 4) * 8;
    const int bid  = lane >> 3;
    const int b_nt = bid >> 1, b_kh = bid & 1;
    const int b_ro = (lane & 7);

    // ---- Q phase: gmem (half) -> smem -> A-fragments via ldmatrix ----
#pragma unroll
    for (int i = 0; i < 8; i++) {
        int idx = tid + i * 128;
        int row = idx >> 3, oc = idx & 7;
        *(uint4*)&sbuf[row * AP + oc * 8] =
            *(const uint4*)(q + base_bn + (size_t)(q_base + row) * EMB + oc * 8);
    }
    __syncthreads();
    uint32_t qf[2][4][4];
    {
        const uint32_t qb = smem_u32(sbuf) + 2 * ((w * 32 + lmro) * AP + lmco);
#pragma unroll
        for (int mt = 0; mt < 2; mt++)
#pragma unroll
            for (int ks = 0; ks < 4; ks++)
                ldmatrix_x4(qf[mt][ks], qb + 2 * (mt * 16 * AP + ks * 16));
    }
    __syncthreads();

    const uint32_t ks_frag_base =
        smem_u32(Ks) + 2 * ((b_nt * 8 + b_ro) * AP + b_kh * 8);
    const uint32_t vs_base = smem_u32(Vs);
    const int lm_row = ((lane >> 3) & 1) * 8 + (lane & 7);
    const int lm_col = (lane >> 4) * 8;

    float o[2][8][4];
#pragma unroll
    for (int mt = 0; mt < 2; mt++)
#pragma unroll
        for (int nt = 0; nt < 8; nt++)
#pragma unroll
            for (int i = 0; i < 4; i++) o[mt][nt][i] = 0.f;

    float mX[2][2] = {{-INFINITY, -INFINITY}, {-INFINITY, -INFINITY}};
    float lX[2][2] = {{0.f, 0.f}, {0.f, 0.f}};

    const int wrow = q_base + w * 32;
    const int nkt = 4 * qt + 4;

    for (int kt = 0; kt < nkt; kt++) {
        // ---- load K,V tiles [32 keys x 64 d] halves (uint4 = 8 halves) ----
#pragma unroll
        for (int i = 0; i < 2; i++) {
            int idx = tid + i * 128;
            int row = idx >> 3, oc = idx & 7;
            size_t g = base_bn + (size_t)(kt * 32 + row) * EMB + oc * 8;
            *(uint4*)&Ks[row * AP + oc * 8] = *(const uint4*)(k + g);
            *(uint4*)&Vs[row * AP + oc * 8] = *(const uint4*)(v + g);
        }
        __syncthreads();

        if (kt * 32 <= wrow + 31) {   // warp-uniform causal skip
            // ---- scores: 4 k16-steps over d=64 ----
            float sc[2][4][4];
#pragma unroll
            for (int mt = 0; mt < 2; mt++)
#pragma unroll
                for (int nt = 0; nt < 4; nt++)
#pragma unroll
                    for (int i = 0; i < 4; i++) sc[mt][nt][i] = 0.f;
#pragma unroll
            for (int ks = 0; ks < 4; ks++) {
                uint32_t bf[4][2];
#pragma unroll
                for (int p = 0; p < 2; p++) {
                    uint32_t r[4];
                    ldmatrix_x4(r, ks_frag_base + 2 * (p * 16 * AP + ks * 16));
                    bf[2 * p][0] = r[0];     bf[2 * p][1] = r[1];
                    bf[2 * p + 1][0] = r[2]; bf[2 * p + 1][1] = r[3];
                }
#pragma unroll
                for (int nt = 0; nt < 4; nt++) {
                    mma_f16(sc[0][nt], qf[0][ks], bf[nt]);
                    mma_f16(sc[1][nt], qf[1][ks], bf[nt]);
                }
            }

            // ---- causal mask (diagonal-overlapping tiles only) ----
            if (kt * 32 + 31 > wrow) {
#pragma unroll
                for (int mt = 0; mt < 2; mt++) {
                    const int ig0 = wrow + mt * 16 + gr;
                    const int ig1 = ig0 + 8;
                    const int jb = kt * 32 + tg * 2;
#pragma unroll
                    for (int nt = 0; nt < 4; nt++) {
                        int jg = jb + nt * 8;
                        if (jg > ig0)     sc[mt][nt][0] = -1e30f;
                        if (jg + 1 > ig0) sc[mt][nt][1] = -1e30f;
                        if (jg > ig1)     sc[mt][nt][2] = -1e30f;
                        if (jg + 1 > ig1) sc[mt][nt][3] = -1e30f;
                    }
                }
            }

            // ---- online softmax per m-tile ----
            const unsigned FULL = 0xffffffffu;
            float aa[2][2];
#pragma unroll
            for (int mt = 0; mt < 2; mt++) {
                float tm0 = sc[mt][0][0], tm1 = sc[mt][0][2];
#pragma unroll
                for (int nt = 0; nt < 4; nt++) {
                    tm0 = fmaxf(tm0, fmaxf(sc[mt][nt][0], sc[mt][nt][1]));
                    tm1 = fmaxf(tm1, fmaxf(sc[mt][nt][2], sc[mt][nt][3]));
                }
                tm0 = fmaxf(tm0, __shfl_xor_sync(FULL, tm0, 1));
                tm0 = fmaxf(tm0, __shfl_xor_sync(FULL, tm0, 2));
                tm1 = fmaxf(tm1, __shfl_xor_sync(FULL, tm1, 1));
                tm1 = fmaxf(tm1, __shfl_xor_sync(FULL, tm1, 2));

                float mn0 = fmaxf(mX[mt][0], tm0), mn1 = fmaxf(mX[mt][1], tm1);
                float a0 = __expf(mX[mt][0] - mn0), a1 = __expf(mX[mt][1] - mn1);
                mX[mt][0] = mn0; mX[mt][1] = mn1;

                float s0 = 0.f, s1 = 0.f;
#pragma unroll
                for (int nt = 0; nt < 4; nt++) {
                    float p00 = __expf(sc[mt][nt][0] - mn0);
                    float p01 = __expf(sc[mt][nt][1] - mn0);
                    float p10 = __expf(sc[mt][nt][2] - mn1);
                    float p11 = __expf(sc[mt][nt][3] - mn1);
                    s0 += p00 + p01; s1 += p10 + p11;
                    sc[mt][nt][0] = p00; sc[mt][nt][1] = p01;
                    sc[mt][nt][2] = p10; sc[mt][nt][3] = p11;
                }
                s0 += __shfl_xor_sync(FULL, s0, 1);
                s0 += __shfl_xor_sync(FULL, s0, 2);
                s1 += __shfl_xor_sync(FULL, s1, 1);
                s1 += __shfl_xor_sync(FULL, s1, 2);
                lX[mt][0] = lX[mt][0] * a0 + s0;
                lX[mt][1] = lX[mt][1] * a1 + s1;
                aa[mt][0] = a0; aa[mt][1] = a1;
            }

            // ---- rescale O ----
#pragma unroll
            for (int mt = 0; mt < 2; mt++)
#pragma unroll
                for (int nt = 0; nt < 8; nt++) {
                    o[mt][nt][0] *= aa[mt][0]; o[mt][nt][1] *= aa[mt][0];
                    o[mt][nt][2] *= aa[mt][1]; o[mt][nt][3] *= aa[mt][1];
                }

            // ---- O += P @ V : P C-frags pack straight into A-frags ----
#pragma unroll
            for (int kg = 0; kg < 2; kg++) {
                uint32_t af[2][4];
#pragma unroll
                for (int mt = 0; mt < 2; mt++) {
                    af[mt][0] = packh2(sc[mt][2 * kg][0], sc[mt][2 * kg][1]);
                    af[mt][1] = packh2(sc[mt][2 * kg][2], sc[mt][2 * kg][3]);
                    af[mt][2] = packh2(sc[mt][2 * kg + 1][0], sc[mt][2 * kg + 1][1]);
                    af[mt][3] = packh2(sc[mt][2 * kg + 1][2], sc[mt][2 * kg + 1][3]);
                }
                const uint32_t rbase =
                    vs_base + 2 * ((kg * 16 + lm_row) * AP + lm_col);
#pragma unroll
                for (int pr = 0; pr < 4; pr++) {
                    uint32_t vb[4];
                    ldmatrix_x4_trans(vb, rbase + 2 * (pr * 16));
                    mma_f16(o[0][2 * pr],     af[0], vb);
                    mma_f16(o[0][2 * pr + 1], af[0], vb + 2);
                    mma_f16(o[1][2 * pr],     af[1], vb);
                    mma_f16(o[1][2 * pr + 1], af[1], vb + 2);
                }
            }
        }
        __syncthreads();   // before next tile overwrites Ks/Vs
    }

    // ---- normalize & store (half) ----
#pragma unroll
    for (int mt = 0; mt < 2; mt++) {
        const float inv0 = 1.f / lX[mt][0], inv1 = 1.f / lX[mt][1];
        const int r0 = wrow + mt * 16 + gr;
#pragma unroll
        for (int nt = 0; nt < 8; nt++) {
            int d = nt * 8 + tg * 2;
            size_t g0 = base_bn + (size_t)r0 * EMB + d;
            size_t g1 = base_bn + (size_t)(r0 + 8) * EMB + d;
            *(uint32_t*)&z[g0] = packh2(o[mt][nt][0] * inv0, o[mt][nt][1] * inv0);
            *(uint32_t*)&z[g1] = packh2(o[mt][nt][2] * inv1, o[mt][nt][3] * inv1);
        }
    }
}

// ---------------------------------------------------------------------------
extern "C" void kernel_launch(void* const* d_in, const int* in_sizes, int n_in,
                              void* d_out, int out_size)
{
    const float* x  = (const float*)d_in[0];
    const float* WQ = (const float*)d_in[1];
    const float* WK = (const float*)d_in[2];
    const float* WV = (const float*)d_in[3];
    const float* WO = (const float*)d_in[4];
    const float* bQ = (const float*)d_in[5];
    const float* bK = (const float*)d_in[6];
    const float* bV = (const float*)d_in[7];
    const float* bO = (const float*)d_in[8];
    float* out = (float*)d_out;

    __half *qp, *kp, *vp, *zp;
    cudaGetSymbolAddress((void**)&qp, g_q);
    cudaGetSymbolAddress((void**)&kp, g_k);
    cudaGetSymbolAddress((void**)&vp, g_v);
    cudaGetSymbolAddress((void**)&zp, g_z);

    gemm_qkv<<<dim3(EMB / 128, BS_TOT / 128, 3), 256>>>(
        x, WQ, WK, WV, bQ, bK, bV, qp, kp, vp);

    attn_tc<<<dim3(SEQ / 128, NHEADS, BATCH), 128>>>(qp, kp, vp, zp);

    gemm_wo<<<dim3(EMB / 128, BS_TOT / 128), 256>>>(zp, WO, bO, out);
}

// round 11
// speedup vs baseline: 9.1199x; 1.0879x over previous
#include <cuda_runtime.h>
#include <cuda_fp16.h>
#include <math.h>
#include <cstdint>

#define BATCH   8
#define SEQ     2048
#define EMB     768
#define NHEADS  12
#define HDIM    64
#define BS_TOT  (BATCH * SEQ)      // 16384

// Scratch (alloc-free rules)
__device__ __half g_x [BS_TOT * EMB];   // x converted to half
__device__ __half g_wq[EMB * EMB];      // W_Q^T: [n*64+h][e]
__device__ __half g_wk[EMB * EMB];
__device__ __half g_wv[EMB * EMB];
__device__ __half g_wo[EMB * EMB];      // W_O^T: [e][n*64+h]
__device__ __half g_q [BS_TOT * EMB];
__device__ __half g_k [BS_TOT * EMB];
__device__ __half g_v [BS_TOT * EMB];
__device__ __half g_z [BS_TOT * EMB];

// ===========================================================================
// Helpers (fp16 m16n8k16 mma, ldmatrix, cp.async; no tcgen05 on compute_103)
// ===========================================================================
__device__ __forceinline__ uint32_t packh2(float lo, float hi) {
    __half2 h = __floats2half2_rn(lo, hi);
    return *(uint32_t*)&h;
}

__device__ __forceinline__ void mma_f16(float* d, const uint32_t* a,
                                        const uint32_t* b) {
    asm volatile(
        "mma.sync.aligned.m16n8k16.row.col.f32.f16.f16.f32 "
        "{%0,%1,%2,%3}, {%4,%5,%6,%7}, {%8,%9}, {%0,%1,%2,%3};"
        : "+f"(d[0]), "+f"(d[1]), "+f"(d[2]), "+f"(d[3])
        : "r"(a[0]), "r"(a[1]), "r"(a[2]), "r"(a[3]),
          "r"(b[0]), "r"(b[1]));
}

__device__ __forceinline__ void ldmatrix_x4(uint32_t* r, uint32_t addr) {
    asm volatile(
        "ldmatrix.sync.aligned.m8n8.x4.shared.b16 {%0,%1,%2,%3}, [%4];"
        : "=r"(r[0]), "=r"(r[1]), "=r"(r[2]), "=r"(r[3]) : "r"(addr));
}
__device__ __forceinline__ void ldmatrix_x4_trans(uint32_t* r, uint32_t addr) {
    asm volatile(
        "ldmatrix.sync.aligned.m8n8.x4.trans.shared.b16 {%0,%1,%2,%3}, [%4];"
        : "=r"(r[0]), "=r"(r[1]), "=r"(r[2]), "=r"(r[3]) : "r"(addr));
}

__device__ __forceinline__ uint32_t smem_u32(const void* p) {
    uint32_t a;
    asm("{ .reg .u64 t; cvta.to.shared.u64 t, %1; cvt.u32.u64 %0, t; }"
        : "=r"(a) : "l"(p));
    return a;
}

#define CP_ASYNC16(sa, gp) \
    asm volatile("cp.async.cg.shared.global [%0], [%1], 16;" \
        :: "r"(sa), "l"(gp))
#define CP_COMMIT() asm volatile("cp.async.commit_group;")
#define CP_WAIT(n)  asm volatile("cp.async.wait_group %0;" :: "n"(n))

// ===========================================================================
// Prep kernels: convert x, transpose+convert weights (run once per launch)
// ===========================================================================
__global__ __launch_bounds__(256) void cvt_x(const float* __restrict__ x) {
    int i = blockIdx.x * 256 + threadIdx.x;          // per float4
    float4 v = ((const float4*)x)[i];
    ((uint2*)g_x)[i] = make_uint2(packh2(v.x, v.y), packh2(v.z, v.w));
}

// W [n][e][h] fp32 -> Wt [n*64+h][e] half.  grid (2, 24, 12), block (32, 8).
__global__ void tr_qkv(const float* __restrict__ W, __half* __restrict__ Wt) {
    __shared__ float t[32][33];
    const int n = blockIdx.z, h0 = blockIdx.x * 32, e0 = blockIdx.y * 32;
    const int tx = threadIdx.x, ty = threadIdx.y;
#pragma unroll
    for (int j = 0; j < 4; j++)
        t[ty + 8 * j][tx] = W[((size_t)n * EMB + e0 + ty + 8 * j) * 64 + h0 + tx];
    __syncthreads();
#pragma unroll
    for (int j = 0; j < 4; j++)
        Wt[((size_t)n * 64 + h0 + ty + 8 * j) * EMB + e0 + tx] =
            __float2half(t[tx][ty + 8 * j]);
}

// W [k][e] fp32 -> Wt [e][k] half.  grid (24, 24), block (32, 8).
__global__ void tr_wo(const float* __restrict__ W) {
    __shared__ float t[32][33];
    const int k0 = blockIdx.x * 32, e0 = blockIdx.y * 32;
    const int tx = threadIdx.x, ty = threadIdx.y;
#pragma unroll
    for (int j = 0; j < 4; j++)
        t[ty + 8 * j][tx] = W[(size_t)(k0 + ty + 8 * j) * EMB + e0 + tx];
    __syncthreads();
#pragma unroll
    for (int j = 0; j < 4; j++)
        g_wo[(size_t)(e0 + ty + 8 * j) * EMB + k0 + tx] =
            __float2half(t[tx][ty + 8 * j]);
}

// ===========================================================================
// Half GEMM body: acc[128x128] = A[M,768] @ B[N,768]^T, 3-stage cp.async.
// 256 threads, 8 warps (wr in 0..1 -> 64 m-rows, wc in 0..3 -> 32 n-cols).
// ===========================================================================
#define GPH   40                      // half pitch (80B = 5x16B)
#define STAGE_H (2 * 128 * GPH)       // halves per stage (A+B)
#define NST   (EMB / 32)              // 24
#define GEMM_SMEM (3 * STAGE_H * 2)   // 61440 B

__device__ __forceinline__ void gemm_body(
    const __half* __restrict__ A, const __half* __restrict__ B,
    __half* smem, float acc[4][4][4], int m0, int n0)
{
    const int tid = threadIdx.x;
    const int wid = tid >> 5, lane = tid & 31;
    const int wr = wid >> 2, wc = wid & 3;
    const int lmro = (lane & 7) + ((lane >> 3) & 1) * 8;
    const int lmco = (lane >> 4) * 8;
    const int b_nt = (lane >> 4), b_kh = (lane >> 3) & 1;
    const int b_ro = lane & 7;
    const int lrow = tid >> 2, loc = tid & 3;   // cp.async mapping

    const uint32_t smb = smem_u32(smem);

    auto issue = [&](int s) {
        const int k0 = s * 32;
        const uint32_t st = smb + (s % 3) * (STAGE_H * 2);
#pragma unroll
        for (int i = 0; i < 2; i++) {
            int row = lrow + i * 64;
            CP_ASYNC16(st + 2 * (row * GPH + loc * 8),
                       A + (size_t)(m0 + row) * EMB + k0 + loc * 8);
            CP_ASYNC16(st + 2 * (128 * GPH + row * GPH + loc * 8),
                       B + (size_t)(n0 + row) * EMB + k0 + loc * 8);
        }
        CP_COMMIT();
    };

    issue(0);
    issue(1);

    for (int s = 0; s < NST; s++) {
        if (s + 2 < NST) { CP_WAIT(1); } else { CP_WAIT(0); }
        __syncthreads();
        if (s + 2 < NST) issue(s + 2);

        const uint32_t st = smb + (s % 3) * (STAGE_H * 2);
        const uint32_t a_base = st + 2 * ((wr * 64 + lmro) * GPH + lmco);
        const uint32_t b_base = st + 2 * (128 * GPH +
                                (wc * 32 + b_nt * 8 + b_ro) * GPH + b_kh * 8);
#pragma unroll
        for (int ks = 0; ks < 2; ks++) {
            const int k0 = ks * 16;
            uint32_t af[4][4], bf[4][2];
#pragma unroll
            for (int mt = 0; mt < 4; mt++)
                ldmatrix_x4(af[mt], a_base + 2 * (mt * 16 * GPH + k0));
#pragma unroll
            for (int p = 0; p < 2; p++) {
                uint32_t r[4];
                ldmatrix_x4(r, b_base + 2 * (p * 16 * GPH + k0));
                bf[2 * p][0] = r[0];     bf[2 * p][1] = r[1];
                bf[2 * p + 1][0] = r[2]; bf[2 * p + 1][1] = r[3];
            }
#pragma unroll
            for (int mt = 0; mt < 4; mt++)
#pragma unroll
                for (int nt = 0; nt < 4; nt++)
                    mma_f16(acc[mt][nt], af[mt], bf[nt]);
        }
    }
}

// QKV projection: half in/out, Q scaled by 1/8 in epilogue.
__global__ __launch_bounds__(256) void gemm_qkv(
    const float* __restrict__ bQ, const float* __restrict__ bK,
    const float* __restrict__ bV)
{
    extern __shared__ __half smem[];
    const __half* Bm = (blockIdx.z == 0) ? g_wq : (blockIdx.z == 1) ? g_wk : g_wv;
    const float* bias = (blockIdx.z == 0) ? bQ : (blockIdx.z == 1) ? bK : bV;
    __half* C = (blockIdx.z == 0) ? g_q : (blockIdx.z == 1) ? g_k : g_v;
    const float qs = (blockIdx.z == 0) ? 0.125f : 1.0f;
    const int m0 = blockIdx.y * 128, n0 = blockIdx.x * 128;

    float acc[4][4][4];
#pragma unroll
    for (int mt = 0; mt < 4; mt++)
#pragma unroll
        for (int nt = 0; nt < 4; nt++)
#pragma unroll
            for (int i = 0; i < 4; i++) acc[mt][nt][i] = 0.f;

    gemm_body(g_x, Bm, smem, acc, m0, n0);

    const int lane = threadIdx.x & 31, wid = threadIdx.x >> 5;
    const int wr = wid >> 2, wc = wid & 3;
    const int gr = lane >> 2, tg = lane & 3;
#pragma unroll
    for (int mt = 0; mt < 4; mt++)
#pragma unroll
        for (int nt = 0; nt < 4; nt++) {
            int r = m0 + wr * 64 + mt * 16 + gr;
            int c = n0 + wc * 32 + nt * 8 + tg * 2;
            float b0 = bias[c], b1 = bias[c + 1];
            *(uint32_t*)&C[(size_t)r * EMB + c] =
                packh2((acc[mt][nt][0] + b0) * qs, (acc[mt][nt][1] + b1) * qs);
            *(uint32_t*)&C[(size_t)(r + 8) * EMB + c] =
                packh2((acc[mt][nt][2] + b0) * qs, (acc[mt][nt][3] + b1) * qs);
        }
}

// Output projection: z (half) @ WO^T -> fp32 out + bias.
__global__ __launch_bounds__(256) void gemm_wo(
    const float* __restrict__ bias, float* __restrict__ C)
{
    extern __shared__ __half smem[];
    const int m0 = blockIdx.y * 128, n0 = blockIdx.x * 128;

    float acc[4][4][4];
#pragma unroll
    for (int mt = 0; mt < 4; mt++)
#pragma unroll
        for (int nt = 0; nt < 4; nt++)
#pragma unroll
            for (int i = 0; i < 4; i++) acc[mt][nt][i] = 0.f;

    gemm_body(g_z, g_wo, smem, acc, m0, n0);

    const int lane = threadIdx.x & 31, wid = threadIdx.x >> 5;
    const int wr = wid >> 2, wc = wid & 3;
    const int gr = lane >> 2, tg = lane & 3;
#pragma unroll
    for (int mt = 0; mt < 4; mt++)
#pragma unroll
        for (int nt = 0; nt < 4; nt++) {
            int r = m0 + wr * 64 + mt * 16 + gr;
            int c = n0 + wc * 32 + nt * 8 + tg * 2;
            float b0 = bias[c], b1 = bias[c + 1];
            *(float2*)(C + (size_t)r * EMB + c) =
                make_float2(acc[mt][nt][0] + b0, acc[mt][nt][1] + b1);
            *(float2*)(C + (size_t)(r + 8) * EMB + c) =
                make_float2(acc[mt][nt][2] + b0, acc[mt][nt][3] + b1);
        }
}

// ===========================================================================
// Flash attention (causal), fp16 m16n8k16, register softmax, all-ldmatrix,
// cp.async double-buffered K/V.  Block = (b, head, 128-query tile), 128 thr.
// ===========================================================================
#define AP 72   // half pitch (144B = 9x16B)

__global__ __launch_bounds__(128) void attn_tc()
{
    __shared__ __half sbuf[128 * AP];   // Q staging aliases double K/V bufs
    const __half* q = g_q; const __half* k = g_k; const __half* v = g_v;

    const int tid = threadIdx.x;
    const int w = tid >> 5, lane = tid & 31;
    const int gr = lane >> 2, tg = lane & 3;
    const int qt = blockIdx.x, hn = blockIdx.y, b = blockIdx.z;
    const int q_base = qt * 128;
    const size_t base_bn = (size_t)b * SEQ * EMB + (size_t)hn * HDIM;

    const int lmro = (lane & 7) + ((lane >> 3) & 1) * 8;
    const int lmco = (lane >> 4) * 8;
    const int b_nt = (lane >> 4), b_kh = (lane >> 3) & 1;
    const int b_ro = lane & 7;

    // ---- Q phase: gmem -> smem -> A-frags via ldmatrix ----
#pragma unroll
    for (int i = 0; i < 8; i++) {
        int idx = tid + i * 128;
        int row = idx >> 3, oc = idx & 7;
        *(uint4*)&sbuf[row * AP + oc * 8] =
            *(const uint4*)(q + base_bn + (size_t)(q_base + row) * EMB + oc * 8);
    }
    __syncthreads();
    uint32_t qf[2][4][4];
    {
        const uint32_t qb = smem_u32(sbuf) + 2 * ((w * 32 + lmro) * AP + lmco);
#pragma unroll
        for (int mt = 0; mt < 2; mt++)
#pragma unroll
            for (int ks = 0; ks < 4; ks++)
                ldmatrix_x4(qf[mt][ks], qb + 2 * (mt * 16 * AP + ks * 16));
    }
    __syncthreads();

    const uint32_t sbu = smem_u32(sbuf);
    const int cprow = tid >> 2, cpoc = tid & 3;   // cp.async mapping
    const int lm_row = ((lane >> 3) & 1) * 8 + (lane & 7);
    const int lm_col = (lane >> 4) * 8;

    const int wrow = q_base + w * 32;
    const int nkt = 4 * qt + 4;

    auto issue_kv = [&](int kt) {
        const uint32_t kd = sbu + (kt & 1) * (64 * AP * 2);
        const uint32_t vd = kd + 32 * AP * 2;
        const size_t g = base_bn + (size_t)(kt * 32 + cprow) * EMB;
#pragma unroll
        for (int i = 0; i < 2; i++) {
            int c = cpoc + i * 4;
            CP_ASYNC16(kd + 2 * (cprow * AP + c * 8), k + g + c * 8);
            CP_ASYNC16(vd + 2 * (cprow * AP + c * 8), v + g + c * 8);
        }
        CP_COMMIT();
    };

    float o[2][8][4];
#pragma unroll
    for (int mt = 0; mt < 2; mt++)
#pragma unroll
        for (int nt = 0; nt < 8; nt++)
#pragma unroll
            for (int i = 0; i < 4; i++) o[mt][nt][i] = 0.f;

    float mX[2][2] = {{-INFINITY, -INFINITY}, {-INFINITY, -INFINITY}};
    float lX[2][2] = {{0.f, 0.f}, {0.f, 0.f}};

    issue_kv(0);

    for (int kt = 0; kt < nkt; kt++) {
        CP_WAIT(0);
        __syncthreads();
        if (kt + 1 < nkt) issue_kv(kt + 1);

        if (kt * 32 <= wrow + 31) {   // warp-uniform causal skip
            const uint32_t kbase = sbu + (kt & 1) * (64 * AP * 2);
            const uint32_t ks_frag_base =
                kbase + 2 * ((b_nt * 8 + b_ro) * AP + b_kh * 8);
            const uint32_t vs_base = kbase + 2 * (32 * AP);

            // ---- scores ----
            float sc[2][4][4];
#pragma unroll
            for (int mt = 0; mt < 2; mt++)
#pragma unroll
                for (int nt = 0; nt < 4; nt++)
#pragma unroll
                    for (int i = 0; i < 4; i++) sc[mt][nt][i] = 0.f;
#pragma unroll
            for (int ks = 0; ks < 4; ks++) {
                uint32_t bf[4][2];
#pragma unroll
                for (int p = 0; p < 2; p++) {
                    uint32_t r[4];
                    ldmatrix_x4(r, ks_frag_base + 2 * (p * 16 * AP + ks * 16));
                    bf[2 * p][0] = r[0];     bf[2 * p][1] = r[1];
                    bf[2 * p + 1][0] = r[2]; bf[2 * p + 1][1] = r[3];
                }
#pragma unroll
                for (int nt = 0; nt < 4; nt++) {
                    mma_f16(sc[0][nt], qf[0][ks], bf[nt]);
                    mma_f16(sc[1][nt], qf[1][ks], bf[nt]);
                }
            }

            // ---- causal mask ----
            if (kt * 32 + 31 > wrow) {
#pragma unroll
                for (int mt = 0; mt < 2; mt++) {
                    const int ig0 = wrow + mt * 16 + gr;
                    const int ig1 = ig0 + 8;
                    const int jb = kt * 32 + tg * 2;
#pragma unroll
                    for (int nt = 0; nt < 4; nt++) {
                        int jg = jb + nt * 8;
                        if (jg > ig0)     sc[mt][nt][0] = -1e30f;
                        if (jg + 1 > ig0) sc[mt][nt][1] = -1e30f;
                        if (jg > ig1)     sc[mt][nt][2] = -1e30f;
                        if (jg + 1 > ig1) sc[mt][nt][3] = -1e30f;
                    }
                }
            }

            // ---- online softmax per m-tile ----
            const unsigned FULL = 0xffffffffu;
            float aa[2][2];
#pragma unroll
            for (int mt = 0; mt < 2; mt++) {
                float tm0 = sc[mt][0][0], tm1 = sc[mt][0][2];
#pragma unroll
                for (int nt = 0; nt < 4; nt++) {
                    tm0 = fmaxf(tm0, fmaxf(sc[mt][nt][0], sc[mt][nt][1]));
                    tm1 = fmaxf(tm1, fmaxf(sc[mt][nt][2], sc[mt][nt][3]));
                }
                tm0 = fmaxf(tm0, __shfl_xor_sync(FULL, tm0, 1));
                tm0 = fmaxf(tm0, __shfl_xor_sync(FULL, tm0, 2));
                tm1 = fmaxf(tm1, __shfl_xor_sync(FULL, tm1, 1));
                tm1 = fmaxf(tm1, __shfl_xor_sync(FULL, tm1, 2));

                float mn0 = fmaxf(mX[mt][0], tm0), mn1 = fmaxf(mX[mt][1], tm1);
                float a0 = __expf(mX[mt][0] - mn0), a1 = __expf(mX[mt][1] - mn1);
                mX[mt][0] = mn0; mX[mt][1] = mn1;

                float s0 = 0.f, s1 = 0.f;
#pragma unroll
                for (int nt = 0; nt < 4; nt++) {
                    float p00 = __expf(sc[mt][nt][0] - mn0);
                    float p01 = __expf(sc[mt][nt][1] - mn0);
                    float p10 = __expf(sc[mt][nt][2] - mn1);
                    float p11 = __expf(sc[mt][nt][3] - mn1);
                    s0 += p00 + p01; s1 += p10 + p11;
                    sc[mt][nt][0] = p00; sc[mt][nt][1] = p01;
                    sc[mt][nt][2] = p10; sc[mt][nt][3] = p11;
                }
                s0 += __shfl_xor_sync(FULL, s0, 1);
                s0 += __shfl_xor_sync(FULL, s0, 2);
                s1 += __shfl_xor_sync(FULL, s1, 1);
                s1 += __shfl_xor_sync(FULL, s1, 2);
                lX[mt][0] = lX[mt][0] * a0 + s0;
                lX[mt][1] = lX[mt][1] * a1 + s1;
                aa[mt][0] = a0; aa[mt][1] = a1;
            }

            // ---- rescale O ----
#pragma unroll
            for (int mt = 0; mt < 2; mt++)
#pragma unroll
                for (int nt = 0; nt < 8; nt++) {
                    o[mt][nt][0] *= aa[mt][0]; o[mt][nt][1] *= aa[mt][0];
                    o[mt][nt][2] *= aa[mt][1]; o[mt][nt][3] *= aa[mt][1];
                }

            // ---- O += P @ V ----
#pragma unroll
            for (int kg = 0; kg < 2; kg++) {
                uint32_t af[2][4];
#pragma unroll
                for (int mt = 0; mt < 2; mt++) {
                    af[mt][0] = packh2(sc[mt][2 * kg][0], sc[mt][2 * kg][1]);
                    af[mt][1] = packh2(sc[mt][2 * kg][2], sc[mt][2 * kg][3]);
                    af[mt][2] = packh2(sc[mt][2 * kg + 1][0], sc[mt][2 * kg + 1][1]);
                    af[mt][3] = packh2(sc[mt][2 * kg + 1][2], sc[mt][2 * kg + 1][3]);
                }
                const uint32_t rbase =
                    vs_base + 2 * ((kg * 16 + lm_row) * AP + lm_col);
#pragma unroll
                for (int pr = 0; pr < 4; pr++) {
                    uint32_t vb[4];
                    ldmatrix_x4_trans(vb, rbase + 2 * (pr * 16));
                    mma_f16(o[0][2 * pr],     af[0], vb);
                    mma_f16(o[0][2 * pr + 1], af[0], vb + 2);
                    mma_f16(o[1][2 * pr],     af[1], vb);
                    mma_f16(o[1][2 * pr + 1], af[1], vb + 2);
                }
            }
        }
    }

    // ---- normalize & store (half) ----
#pragma unroll
    for (int mt = 0; mt < 2; mt++) {
        const float inv0 = 1.f / lX[mt][0], inv1 = 1.f / lX[mt][1];
        const int r0 = wrow + mt * 16 + gr;
#pragma unroll
        for (int nt = 0; nt < 8; nt++) {
            int d = nt * 8 + tg * 2;
            size_t g0 = base_bn + (size_t)r0 * EMB + d;
            size_t g1 = base_bn + (size_t)(r0 + 8) * EMB + d;
            *(uint32_t*)&g_z[g0] = packh2(o[mt][nt][0] * inv0, o[mt][nt][1] * inv0);
            *(uint32_t*)&g_z[g1] = packh2(o[mt][nt][2] * inv1, o[mt][nt][3] * inv1);
        }
    }
}

// ---------------------------------------------------------------------------
extern "C" void kernel_launch(void* const* d_in, const int* in_sizes, int n_in,
                              void* d_out, int out_size)
{
    const float* x  = (const float*)d_in[0];
    const float* WQ = (const float*)d_in[1];
    const float* WK = (const float*)d_in[2];
    const float* WV = (const float*)d_in[3];
    const float* WO = (const float*)d_in[4];
    const float* bQ = (const float*)d_in[5];
    const float* bK = (const float*)d_in[6];
    const float* bV = (const float*)d_in[7];
    const float* bO = (const float*)d_in[8];
    float* out = (float*)d_out;

    __half *wqp, *wkp, *wvp;
    cudaGetSymbolAddress((void**)&wqp, g_wq);
    cudaGetSymbolAddress((void**)&wkp, g_wk);
    cudaGetSymbolAddress((void**)&wvp, g_wv);

    cudaFuncSetAttribute(gemm_qkv,
        cudaFuncAttributeMaxDynamicSharedMemorySize, GEMM_SMEM);
    cudaFuncSetAttribute(gemm_wo,
        cudaFuncAttributeMaxDynamicSharedMemorySize, GEMM_SMEM);

    // ---- prep: convert x, transpose+convert weights ----
    cvt_x<<<BS_TOT * EMB / 4 / 256, 256>>>(x);
    tr_qkv<<<dim3(2, 24, 12), dim3(32, 8)>>>(WQ, wqp);
    tr_qkv<<<dim3(2, 24, 12), dim3(32, 8)>>>(WK, wkp);
    tr_qkv<<<dim3(2, 24, 12), dim3(32, 8)>>>(WV, wvp);
    tr_wo<<<dim3(24, 24), dim3(32, 8)>>>(WO);

    // ---- main pipeline ----
    gemm_qkv<<<dim3(EMB / 128, BS_TOT / 128, 3), 256, GEMM_SMEM>>>(bQ, bK, bV);
    attn_tc<<<dim3(SEQ / 128, NHEADS, BATCH), 128>>>();
    gemm_wo<<<dim3(EMB / 128, BS_TOT / 128), 256, GEMM_SMEM>>>(bO, out);
}